// round 2
// baseline (speedup 1.0000x reference)
#include <cuda_runtime.h>
#include <cuda_bf16.h>
#include <math.h>

// Problem constants
#define BATCH 2
#define SEQ   2048
#define EMBD  1024
#define NHEAD 16
#define HDIM  64
#define BT    (BATCH*SEQ)          // 4096
#define QKVN  (3*EMBD)             // 3072

// ---------------- scratch (device globals; no runtime allocation) ----------------
__device__ float g_qkv[BT * QKVN];                 // [B*T, 3C]
__device__ float g_q[BATCH * NHEAD * SEQ * HDIM];  // [B,H,T,D]
__device__ float g_k[BATCH * NHEAD * SEQ * HDIM];
__device__ float g_v[BATCH * NHEAD * SEQ * HDIM];
__device__ float g_att[BT * EMBD];                 // [B,T,C]

// ---------------- generic SGEMM: C[M,N] = A[M,K] @ B[K,N] + bias[N] ----------------
__global__ __launch_bounds__(256) void sgemm_bias(
    const float* __restrict__ A, const float* __restrict__ B,
    const float* __restrict__ bias, float* __restrict__ C,
    int M, int N, int K)
{
    __shared__ float As[16][128];   // As[k][m]
    __shared__ float Bs[16][132];   // Bs[k][n] (padded)

    const int tid = threadIdx.x;
    const int ty = tid >> 4;
    const int tx = tid & 15;
    const int m0 = blockIdx.y * 128;
    const int n0 = blockIdx.x * 128;

    float acc[8][8];
#pragma unroll
    for (int i = 0; i < 8; i++)
#pragma unroll
        for (int j = 0; j < 8; j++) acc[i][j] = 0.f;

    for (int k0 = 0; k0 < K; k0 += 16) {
#pragma unroll
        for (int it = 0; it < 2; it++) {
            int idx = tid + it * 256;
            int ar = idx >> 2;
            int a4 = (idx & 3) << 2;
            float4 v = *(const float4*)(A + (size_t)(m0 + ar) * K + k0 + a4);
            As[a4 + 0][ar] = v.x;
            As[a4 + 1][ar] = v.y;
            As[a4 + 2][ar] = v.z;
            As[a4 + 3][ar] = v.w;
        }
#pragma unroll
        for (int it = 0; it < 2; it++) {
            int idx = tid + it * 256;
            int br = idx >> 5;
            int b4 = (idx & 31) << 2;
            *(float4*)(&Bs[br][b4]) = *(const float4*)(B + (size_t)(k0 + br) * N + n0 + b4);
        }
        __syncthreads();

#pragma unroll
        for (int kk = 0; kk < 16; kk++) {
            float a[8], b[8];
            *(float4*)(a)     = *(const float4*)(&As[kk][ty * 8]);
            *(float4*)(a + 4) = *(const float4*)(&As[kk][ty * 8 + 4]);
            *(float4*)(b)     = *(const float4*)(&Bs[kk][tx * 8]);
            *(float4*)(b + 4) = *(const float4*)(&Bs[kk][tx * 8 + 4]);
#pragma unroll
            for (int i = 0; i < 8; i++)
#pragma unroll
                for (int j = 0; j < 8; j++)
                    acc[i][j] = fmaf(a[i], b[j], acc[i][j]);
        }
        __syncthreads();
    }

#pragma unroll
    for (int i = 0; i < 8; i++) {
        int m = m0 + ty * 8 + i;
        float* crow = C + (size_t)m * N + n0 + tx * 8;
        const float* brow = bias + n0 + tx * 8;
#pragma unroll
        for (int j4 = 0; j4 < 2; j4++) {
            float4 bv = *(const float4*)(brow + j4 * 4);
            float4 o;
            o.x = acc[i][j4 * 4 + 0] + bv.x;
            o.y = acc[i][j4 * 4 + 1] + bv.y;
            o.z = acc[i][j4 * 4 + 2] + bv.z;
            o.w = acc[i][j4 * 4 + 3] + bv.w;
            *(float4*)(crow + j4 * 4) = o;
        }
    }
}

// ---------------- RoPE + transpose/scatter qkv -> q,k,v in [B,H,T,D] ----------------
__global__ __launch_bounds__(256) void rope_scatter(
    const float* __restrict__ cosb, const float* __restrict__ sinb)
{
    int idx = blockIdx.x * 256 + threadIdx.x;
    int i = idx & 31;
    int h = (idx >> 5) & 15;
    int t = (idx >> 9) & 2047;
    int b = idx >> 20;

    const float c = cosb[t * 32 + i];
    const float s = sinb[t * 32 + i];

    size_t rowq = ((size_t)(b * SEQ + t)) * QKVN + h * HDIM + 2 * i;
    float2 q = *(const float2*)(g_qkv + rowq);
    float2 k = *(const float2*)(g_qkv + rowq + EMBD);
    float2 v = *(const float2*)(g_qkv + rowq + 2 * EMBD);

    size_t o = (((size_t)(b * NHEAD + h) * SEQ + t)) * HDIM + 2 * i;
    *(float2*)(g_q + o) = make_float2(q.x * c - q.y * s, q.x * s + q.y * c);
    *(float2*)(g_k + o) = make_float2(k.x * c - k.y * s, k.x * s + k.y * c);
    *(float2*)(g_v + o) = v;
}

// ---------------- tf32 mma helpers ----------------
__device__ __forceinline__ unsigned f2tf(float x) {
    unsigned u;
    asm("cvt.rna.tf32.f32 %0, %1;" : "=r"(u) : "f"(x));
    return u;
}

__device__ __forceinline__ void mma8(float* c,
    unsigned a0, unsigned a1, unsigned a2, unsigned a3,
    unsigned b0, unsigned b1)
{
    asm volatile(
        "mma.sync.aligned.m16n8k8.row.col.f32.tf32.tf32.f32 "
        "{%0,%1,%2,%3},{%4,%5,%6,%7},{%8,%9},{%0,%1,%2,%3};"
        : "+f"(c[0]), "+f"(c[1]), "+f"(c[2]), "+f"(c[3])
        : "r"(a0), "r"(a1), "r"(a2), "r"(a3), "r"(b0), "r"(b1));
}

// ---------------- flash attention, tf32 tensor-core, causal ----------------
// 128 threads = 4 warps; block handles 64 query rows (warp w: rows 16w..16w+15);
// iterates 64-key tiles with online softmax. All operands staged in smem as
// tf32 bit patterns; fragment loads are bank-conflict-free with pitch 68.
#define APAD 68
__global__ __launch_bounds__(128) void attn_mma()
{
    extern __shared__ unsigned smu[];
    unsigned* Qs = smu;                    // 64*68
    unsigned* Ks = smu + 64 * APAD;
    unsigned* Vs = smu + 2 * 64 * APAD;
    unsigned* Ps = smu + 3 * 64 * APAD;

    const int qt = (int)gridDim.x - 1 - (int)blockIdx.x;  // long blocks first
    const int bh = blockIdx.y;
    const int b  = bh >> 4;
    const int h  = bh & 15;
    const float* qp = g_q + (size_t)bh * SEQ * HDIM;
    const float* kp = g_k + (size_t)bh * SEQ * HDIM;
    const float* vp = g_v + (size_t)bh * SEQ * HDIM;
    const int q0 = qt * 64;

    const int tid  = threadIdx.x;
    const int w    = tid >> 5;
    const int lane = tid & 31;
    const int grp  = lane >> 2;   // 0..7
    const int t4   = lane & 3;    // 0..3
    const int w16  = w * 16;

    // load Q tile (tf32-converted), vectorized
#pragma unroll
    for (int it = 0; it < 8; it++) {
        int slot = tid + it * 128;          // 0..1023
        int r = slot >> 4;
        int c4 = (slot & 15) << 2;
        float4 v = *(const float4*)(qp + (size_t)(q0 + r) * HDIM + c4);
        uint4 u = make_uint4(f2tf(v.x), f2tf(v.y), f2tf(v.z), f2tf(v.w));
        *(uint4*)(Qs + r * APAD + c4) = u;
    }

    float O[8][4];
#pragma unroll
    for (int nc = 0; nc < 8; nc++)
#pragma unroll
        for (int j = 0; j < 4; j++) O[nc][j] = 0.f;
    float m0 = -INFINITY, m1 = -INFINITY, l0 = 0.f, l1 = 0.f;

    for (int kt = 0; kt <= qt; kt++) {
        const int k0 = kt * 64;
        __syncthreads();
        // load K, V tiles (tf32)
#pragma unroll
        for (int it = 0; it < 8; it++) {
            int slot = tid + it * 128;
            int r = slot >> 4;
            int c4 = (slot & 15) << 2;
            float4 kv = *(const float4*)(kp + (size_t)(k0 + r) * HDIM + c4);
            float4 vv = *(const float4*)(vp + (size_t)(k0 + r) * HDIM + c4);
            *(uint4*)(Ks + r * APAD + c4) = make_uint4(f2tf(kv.x), f2tf(kv.y), f2tf(kv.z), f2tf(kv.w));
            *(uint4*)(Vs + r * APAD + c4) = make_uint4(f2tf(vv.x), f2tf(vv.y), f2tf(vv.z), f2tf(vv.w));
        }
        __syncthreads();

        // ---- S = Q K^T ----
        float S[8][4];
#pragma unroll
        for (int nc = 0; nc < 8; nc++)
#pragma unroll
            for (int j = 0; j < 4; j++) S[nc][j] = 0.f;

#pragma unroll
        for (int kc = 0; kc < 8; kc++) {
            const unsigned* qrow0 = Qs + (w16 + grp) * APAD + kc * 8;
            const unsigned* qrow1 = Qs + (w16 + grp + 8) * APAD + kc * 8;
            unsigned a0 = qrow0[t4];
            unsigned a1 = qrow1[t4];
            unsigned a2 = qrow0[t4 + 4];
            unsigned a3 = qrow1[t4 + 4];
#pragma unroll
            for (int nc = 0; nc < 8; nc++) {
                const unsigned* krow = Ks + (nc * 8 + grp) * APAD + kc * 8;
                mma8(S[nc], a0, a1, a2, a3, krow[t4], krow[t4 + 4]);
            }
        }

        // ---- scale + causal mask ----
        const bool diag = (kt == qt);
        const int lr0 = w16 + grp;        // local row for c0,c1
        const int lr1 = w16 + grp + 8;    // local row for c2,c3
#pragma unroll
        for (int nc = 0; nc < 8; nc++) {
            int lc = nc * 8 + 2 * t4;
#pragma unroll
            for (int j = 0; j < 4; j++) S[nc][j] *= 0.125f;
            if (diag) {
                if (lc     > lr0) S[nc][0] = -INFINITY;
                if (lc + 1 > lr0) S[nc][1] = -INFINITY;
                if (lc     > lr1) S[nc][2] = -INFINITY;
                if (lc + 1 > lr1) S[nc][3] = -INFINITY;
            }
        }

        // ---- online softmax (per-row, quad-redundant) ----
        float mx0 = -INFINITY, mx1 = -INFINITY;
#pragma unroll
        for (int nc = 0; nc < 8; nc++) {
            mx0 = fmaxf(mx0, fmaxf(S[nc][0], S[nc][1]));
            mx1 = fmaxf(mx1, fmaxf(S[nc][2], S[nc][3]));
        }
        mx0 = fmaxf(mx0, __shfl_xor_sync(0xffffffffu, mx0, 1));
        mx0 = fmaxf(mx0, __shfl_xor_sync(0xffffffffu, mx0, 2));
        mx1 = fmaxf(mx1, __shfl_xor_sync(0xffffffffu, mx1, 1));
        mx1 = fmaxf(mx1, __shfl_xor_sync(0xffffffffu, mx1, 2));

        float mn0 = fmaxf(m0, mx0);
        float mn1 = fmaxf(m1, mx1);
        float al0 = __expf(m0 - mn0);
        float al1 = __expf(m1 - mn1);
        m0 = mn0; m1 = mn1;

        float sum0 = 0.f, sum1 = 0.f;
        unsigned* prow0 = Ps + lr0 * APAD;
        unsigned* prow1 = Ps + lr1 * APAD;
#pragma unroll
        for (int nc = 0; nc < 8; nc++) {
            float p0 = __expf(S[nc][0] - mn0);
            float p1 = __expf(S[nc][1] - mn0);
            float p2 = __expf(S[nc][2] - mn1);
            float p3 = __expf(S[nc][3] - mn1);
            sum0 += p0 + p1;
            sum1 += p2 + p3;
            int lc = nc * 8 + 2 * t4;
            prow0[lc]     = f2tf(p0);
            prow0[lc + 1] = f2tf(p1);
            prow1[lc]     = f2tf(p2);
            prow1[lc + 1] = f2tf(p3);
        }
        sum0 += __shfl_xor_sync(0xffffffffu, sum0, 1);
        sum0 += __shfl_xor_sync(0xffffffffu, sum0, 2);
        sum1 += __shfl_xor_sync(0xffffffffu, sum1, 1);
        sum1 += __shfl_xor_sync(0xffffffffu, sum1, 2);
        l0 = l0 * al0 + sum0;
        l1 = l1 * al1 + sum1;

        // rescale O
#pragma unroll
        for (int nc = 0; nc < 8; nc++) {
            O[nc][0] *= al0; O[nc][1] *= al0;
            O[nc][2] *= al1; O[nc][3] *= al1;
        }

        __syncwarp();

        // ---- O += P V ----
#pragma unroll
        for (int kc = 0; kc < 8; kc++) {
            const unsigned* pr0 = Ps + (w16 + grp) * APAD + kc * 8;
            const unsigned* pr1 = Ps + (w16 + grp + 8) * APAD + kc * 8;
            unsigned a0 = pr0[t4];
            unsigned a1 = pr1[t4];
            unsigned a2 = pr0[t4 + 4];
            unsigned a3 = pr1[t4 + 4];
#pragma unroll
            for (int nc = 0; nc < 8; nc++) {
                unsigned b0 = Vs[(kc * 8 + t4)     * APAD + nc * 8 + grp];
                unsigned b1 = Vs[(kc * 8 + t4 + 4) * APAD + nc * 8 + grp];
                mma8(O[nc], a0, a1, a2, a3, b0, b1);
            }
        }
    }

    // ---- epilogue: normalize, write to [B,T,C] ----
    float inv0 = 1.f / l0;
    float inv1 = 1.f / l1;
    size_t base0 = ((size_t)(b * SEQ + q0 + w16 + grp))     * EMBD + h * HDIM;
    size_t base1 = ((size_t)(b * SEQ + q0 + w16 + grp + 8)) * EMBD + h * HDIM;
#pragma unroll
    for (int nc = 0; nc < 8; nc++) {
        int lc = nc * 8 + 2 * t4;
        *(float2*)(g_att + base0 + lc) = make_float2(O[nc][0] * inv0, O[nc][1] * inv0);
        *(float2*)(g_att + base1 + lc) = make_float2(O[nc][2] * inv1, O[nc][3] * inv1);
    }
}

// ---------------- launcher ----------------
extern "C" void kernel_launch(void* const* d_in, const int* in_sizes, int n_in,
                              void* d_out, int out_size)
{
    const float* x     = (const float*)d_in[0];
    const float* Wqkv  = (const float*)d_in[1];
    const float* bqkv  = (const float*)d_in[2];
    const float* Wproj = (const float*)d_in[3];
    const float* bproj = (const float*)d_in[4];
    const float* cosb  = (const float*)d_in[5];
    const float* sinb  = (const float*)d_in[6];
    float* out = (float*)d_out;

    void *p_qkv = nullptr, *p_att = nullptr;
    cudaGetSymbolAddress(&p_qkv, g_qkv);
    cudaGetSymbolAddress(&p_att, g_att);

    // 1) QKV GEMM: [4096,1024] @ [1024,3072] + bias
    sgemm_bias<<<dim3(QKVN / 128, BT / 128), 256>>>(
        x, Wqkv, bqkv, (float*)p_qkv, BT, QKVN, EMBD);

    // 2) RoPE + transpose to [B,H,T,D]
    rope_scatter<<<(BATCH * SEQ * NHEAD * (HDIM / 2)) / 256, 256>>>(cosb, sinb);

    // 3) causal flash attention (tf32 tensor cores)
    const int smem_bytes = 4 * 64 * APAD * sizeof(unsigned);   // 69632
    cudaFuncSetAttribute(attn_mma, cudaFuncAttributeMaxDynamicSharedMemorySize, smem_bytes);
    attn_mma<<<dim3(SEQ / 64, BATCH * NHEAD), 128, smem_bytes>>>();

    // 4) output projection: [4096,1024] @ [1024,1024] + bias
    sgemm_bias<<<dim3(EMBD / 128, BT / 128), 256>>>(
        (const float*)p_att, Wproj, bproj, out, BT, EMBD, EMBD);
}

// round 3
// speedup vs baseline: 2.9834x; 2.9834x over previous
#include <cuda_runtime.h>
#include <cuda_bf16.h>
#include <math.h>

// Problem constants
#define BATCH 2
#define SEQ   2048
#define EMBD  1024
#define NHEAD 16
#define HDIM  64
#define BT    (BATCH*SEQ)          // 4096
#define QKVN  (3*EMBD)             // 3072

// ---------------- scratch (device globals; no runtime allocation) ----------------
__device__ float g_qkv[BT * QKVN];                 // [B*T, 3C]
__device__ float g_q[BATCH * NHEAD * SEQ * HDIM];  // [B,H,T,D]
__device__ float g_k[BATCH * NHEAD * SEQ * HDIM];
__device__ float g_v[BATCH * NHEAD * SEQ * HDIM];
__device__ float g_att[BT * EMBD];                 // [B,T,C]

// ---------------- tf32 helpers ----------------
__device__ __forceinline__ unsigned f2tf(float x) {
    unsigned u;
    asm("cvt.rna.tf32.f32 %0, %1;" : "=r"(u) : "f"(x));
    return u;
}

__device__ __forceinline__ void mma8(float* c,
    unsigned a0, unsigned a1, unsigned a2, unsigned a3,
    unsigned b0, unsigned b1)
{
    asm volatile(
        "mma.sync.aligned.m16n8k8.row.col.f32.tf32.tf32.f32 "
        "{%0,%1,%2,%3},{%4,%5,%6,%7},{%8,%9},{%0,%1,%2,%3};"
        : "+f"(c[0]), "+f"(c[1]), "+f"(c[2]), "+f"(c[3])
        : "r"(a0), "r"(a1), "r"(a2), "r"(a3), "r"(b0), "r"(b1));
}

// ---------------- tf32 tensor-core GEMM: C[M,N] = A[M,K] @ B[K,N] + bias ----------------
// 256 threads = 8 warps; BM=128, BN=128, BK=16; warp computes 32x64.
#define GP_A 20     // A smem pitch (floats): 20 % 32 ensures conflict-free frags
#define GP_B 136    // B smem pitch: 136 % 32 == 8 -> conflict-free frags
__global__ __launch_bounds__(256) void gemm_tf32(
    const float* __restrict__ A, const float* __restrict__ B,
    const float* __restrict__ bias, float* __restrict__ C,
    int M, int N, int K)
{
    __shared__ unsigned As[128 * GP_A];   // [m][k]
    __shared__ unsigned Bs[16 * GP_B];    // [k][n]

    const int tid  = threadIdx.x;
    const int w    = tid >> 5;
    const int lane = tid & 31;
    const int grp  = lane >> 2;
    const int t4   = lane & 3;
    const int wr   = w >> 1;          // 0..3
    const int wc   = w & 1;           // 0..1
    const int mw   = wr * 32;
    const int nw   = wc * 64;
    const int m0   = blockIdx.y * 128;
    const int n0   = blockIdx.x * 128;

    float acc[2][8][4];
#pragma unroll
    for (int mf = 0; mf < 2; mf++)
#pragma unroll
        for (int nc = 0; nc < 8; nc++)
#pragma unroll
            for (int j = 0; j < 4; j++) acc[mf][nc][j] = 0.f;

    for (int k0 = 0; k0 < K; k0 += 16) {
        // stage A 128x16 (convert to tf32)
#pragma unroll
        for (int it = 0; it < 2; it++) {
            int idx = tid + it * 256;
            int ar = idx >> 2;
            int c4 = (idx & 3) << 2;
            float4 v = *(const float4*)(A + (size_t)(m0 + ar) * K + k0 + c4);
            uint4 u = make_uint4(f2tf(v.x), f2tf(v.y), f2tf(v.z), f2tf(v.w));
            *(uint4*)(As + ar * GP_A + c4) = u;
        }
        // stage B 16x128
#pragma unroll
        for (int it = 0; it < 2; it++) {
            int idx = tid + it * 256;
            int br = idx >> 5;
            int b4 = (idx & 31) << 2;
            float4 v = *(const float4*)(B + (size_t)(k0 + br) * N + n0 + b4);
            uint4 u = make_uint4(f2tf(v.x), f2tf(v.y), f2tf(v.z), f2tf(v.w));
            *(uint4*)(Bs + br * GP_B + b4) = u;
        }
        __syncthreads();

#pragma unroll
        for (int ks = 0; ks < 16; ks += 8) {
            unsigned a[2][4];
#pragma unroll
            for (int mf = 0; mf < 2; mf++) {
                const unsigned* r0 = As + (mw + mf * 16 + grp) * GP_A + ks;
                const unsigned* r1 = As + (mw + mf * 16 + grp + 8) * GP_A + ks;
                a[mf][0] = r0[t4];
                a[mf][1] = r1[t4];
                a[mf][2] = r0[t4 + 4];
                a[mf][3] = r1[t4 + 4];
            }
#pragma unroll
            for (int nc = 0; nc < 8; nc++) {
                unsigned b0 = Bs[(ks + t4) * GP_B + nw + nc * 8 + grp];
                unsigned b1 = Bs[(ks + t4 + 4) * GP_B + nw + nc * 8 + grp];
                mma8(acc[0][nc], a[0][0], a[0][1], a[0][2], a[0][3], b0, b1);
                mma8(acc[1][nc], a[1][0], a[1][1], a[1][2], a[1][3], b0, b1);
            }
        }
        __syncthreads();
    }

    // epilogue
#pragma unroll
    for (int mf = 0; mf < 2; mf++) {
#pragma unroll
        for (int h = 0; h < 2; h++) {
            int m = m0 + mw + mf * 16 + h * 8 + grp;
            float* crow = C + (size_t)m * N + n0 + nw;
#pragma unroll
            for (int nc = 0; nc < 8; nc++) {
                int c = nc * 8 + 2 * t4;
                float2 o;
                o.x = acc[mf][nc][2 * h]     + bias[n0 + nw + c];
                o.y = acc[mf][nc][2 * h + 1] + bias[n0 + nw + c + 1];
                *(float2*)(crow + c) = o;
            }
        }
    }
}

// ---------------- RoPE + transpose/scatter qkv -> q,k,v in [B,H,T,D] ----------------
__global__ __launch_bounds__(256) void rope_scatter(
    const float* __restrict__ cosb, const float* __restrict__ sinb)
{
    int idx = blockIdx.x * 256 + threadIdx.x;
    int i = idx & 31;
    int h = (idx >> 5) & 15;
    int t = (idx >> 9) & 2047;
    int b = idx >> 20;

    const float c = cosb[t * 32 + i];
    const float s = sinb[t * 32 + i];

    size_t rowq = ((size_t)(b * SEQ + t)) * QKVN + h * HDIM + 2 * i;
    float2 q = *(const float2*)(g_qkv + rowq);
    float2 k = *(const float2*)(g_qkv + rowq + EMBD);
    float2 v = *(const float2*)(g_qkv + rowq + 2 * EMBD);

    size_t o = (((size_t)(b * NHEAD + h) * SEQ + t)) * HDIM + 2 * i;
    *(float2*)(g_q + o) = make_float2(q.x * c - q.y * s, q.x * s + q.y * c);
    *(float2*)(g_k + o) = make_float2(k.x * c - k.y * s, k.x * s + k.y * c);
    *(float2*)(g_v + o) = v;
}

// ---------------- flash attention, tf32 tensor cores, causal ----------------
// 128 threads = 4 warps; CTA = 128 query rows; warp w owns rows 32w..32w+31
// (2 m16 fragments). Key tiles of 64. Pitch 68 (== 4 mod 32): conflict-free.
#define APAD 68
__global__ __launch_bounds__(128) void attn_mma()
{
    extern __shared__ unsigned smu[];
    unsigned* Qs = smu;                     // 128*68
    unsigned* Ks = smu + 128 * APAD;        //  64*68
    unsigned* Vs = smu + 192 * APAD;        //  64*68
    unsigned* Ps = smu + 256 * APAD;        // 128*68

    const int qt = (int)gridDim.x - 1 - (int)blockIdx.x;  // long blocks first
    const int bh = blockIdx.y;
    const int b  = bh >> 4;
    const int h  = bh & 15;
    const float* qp = g_q + (size_t)bh * SEQ * HDIM;
    const float* kp = g_k + (size_t)bh * SEQ * HDIM;
    const float* vp = g_v + (size_t)bh * SEQ * HDIM;
    const int q0 = qt * 128;

    const int tid  = threadIdx.x;
    const int w    = tid >> 5;
    const int lane = tid & 31;
    const int grp  = lane >> 2;
    const int t4   = lane & 3;
    const int mw   = w * 32;

    // load Q tile 128x64 (tf32)
#pragma unroll
    for (int it = 0; it < 16; it++) {
        int slot = tid + it * 128;
        int r = slot >> 4;
        int c4 = (slot & 15) << 2;
        float4 v = *(const float4*)(qp + (size_t)(q0 + r) * HDIM + c4);
        *(uint4*)(Qs + r * APAD + c4) = make_uint4(f2tf(v.x), f2tf(v.y), f2tf(v.z), f2tf(v.w));
    }

    float O[2][8][4];
#pragma unroll
    for (int mf = 0; mf < 2; mf++)
#pragma unroll
        for (int nc = 0; nc < 8; nc++)
#pragma unroll
            for (int j = 0; j < 4; j++) O[mf][nc][j] = 0.f;
    float mrow[2][2], lrow[2][2];
#pragma unroll
    for (int mf = 0; mf < 2; mf++)
#pragma unroll
        for (int hh = 0; hh < 2; hh++) { mrow[mf][hh] = -INFINITY; lrow[mf][hh] = 0.f; }

    const int kt_max = 2 * qt + 1;
    for (int kt = 0; kt <= kt_max; kt++) {
        const int k0 = kt * 64;
        __syncthreads();
        // load K, V tiles 64x64 (tf32)
#pragma unroll
        for (int it = 0; it < 8; it++) {
            int slot = tid + it * 128;
            int r = slot >> 4;
            int c4 = (slot & 15) << 2;
            float4 kv = *(const float4*)(kp + (size_t)(k0 + r) * HDIM + c4);
            float4 vv = *(const float4*)(vp + (size_t)(k0 + r) * HDIM + c4);
            *(uint4*)(Ks + r * APAD + c4) = make_uint4(f2tf(kv.x), f2tf(kv.y), f2tf(kv.z), f2tf(kv.w));
            *(uint4*)(Vs + r * APAD + c4) = make_uint4(f2tf(vv.x), f2tf(vv.y), f2tf(vv.z), f2tf(vv.w));
        }
        __syncthreads();

        // ---- S = Q K^T ----
        float S[2][8][4];
#pragma unroll
        for (int mf = 0; mf < 2; mf++)
#pragma unroll
            for (int nc = 0; nc < 8; nc++)
#pragma unroll
                for (int j = 0; j < 4; j++) S[mf][nc][j] = 0.f;

#pragma unroll
        for (int kc = 0; kc < 8; kc++) {
            unsigned a[2][4];
#pragma unroll
            for (int mf = 0; mf < 2; mf++) {
                const unsigned* r0 = Qs + (mw + mf * 16 + grp) * APAD + kc * 8;
                const unsigned* r1 = Qs + (mw + mf * 16 + grp + 8) * APAD + kc * 8;
                a[mf][0] = r0[t4];
                a[mf][1] = r1[t4];
                a[mf][2] = r0[t4 + 4];
                a[mf][3] = r1[t4 + 4];
            }
#pragma unroll
            for (int nc = 0; nc < 8; nc++) {
                const unsigned* krow = Ks + (nc * 8 + grp) * APAD + kc * 8;
                unsigned b0 = krow[t4];
                unsigned b1 = krow[t4 + 4];
                mma8(S[0][nc], a[0][0], a[0][1], a[0][2], a[0][3], b0, b1);
                mma8(S[1][nc], a[1][0], a[1][1], a[1][2], a[1][3], b0, b1);
            }
        }

        // ---- scale + causal mask ----
        const bool need_mask = (k0 + 63 > q0 + mw);
#pragma unroll
        for (int mf = 0; mf < 2; mf++) {
#pragma unroll
            for (int nc = 0; nc < 8; nc++) {
#pragma unroll
                for (int j = 0; j < 4; j++) S[mf][nc][j] *= 0.125f;
                if (need_mask) {
                    int col = k0 + nc * 8 + 2 * t4;
                    int r0g = q0 + mw + mf * 16 + grp;
                    int r1g = r0g + 8;
                    if (col     > r0g) S[mf][nc][0] = -INFINITY;
                    if (col + 1 > r0g) S[mf][nc][1] = -INFINITY;
                    if (col     > r1g) S[mf][nc][2] = -INFINITY;
                    if (col + 1 > r1g) S[mf][nc][3] = -INFINITY;
                }
            }
        }

        // ---- online softmax + write P (tf32) ----
#pragma unroll
        for (int mf = 0; mf < 2; mf++) {
#pragma unroll
            for (int hh = 0; hh < 2; hh++) {
                float mx = -INFINITY;
#pragma unroll
                for (int nc = 0; nc < 8; nc++)
                    mx = fmaxf(mx, fmaxf(S[mf][nc][2 * hh], S[mf][nc][2 * hh + 1]));
                mx = fmaxf(mx, __shfl_xor_sync(0xffffffffu, mx, 1));
                mx = fmaxf(mx, __shfl_xor_sync(0xffffffffu, mx, 2));

                float mold = mrow[mf][hh];
                float mnew = fmaxf(mold, mx);
                float al   = __expf(mold - mnew);
                mrow[mf][hh] = mnew;

                unsigned* prow = Ps + (mw + mf * 16 + hh * 8 + grp) * APAD;
                float sum = 0.f;
#pragma unroll
                for (int nc = 0; nc < 8; nc++) {
                    float p0 = __expf(S[mf][nc][2 * hh]     - mnew);
                    float p1 = __expf(S[mf][nc][2 * hh + 1] - mnew);
                    sum += p0 + p1;
                    *(uint2*)(prow + nc * 8 + 2 * t4) = make_uint2(f2tf(p0), f2tf(p1));
                }
                sum += __shfl_xor_sync(0xffffffffu, sum, 1);
                sum += __shfl_xor_sync(0xffffffffu, sum, 2);
                lrow[mf][hh] = lrow[mf][hh] * al + sum;

                // rescale O rows for this (mf,hh)
#pragma unroll
                for (int nc = 0; nc < 8; nc++) {
                    O[mf][nc][2 * hh]     *= al;
                    O[mf][nc][2 * hh + 1] *= al;
                }
            }
        }
        __syncwarp();

        // ---- O += P V ----
#pragma unroll
        for (int kc = 0; kc < 8; kc++) {
            unsigned a[2][4];
#pragma unroll
            for (int mf = 0; mf < 2; mf++) {
                const unsigned* r0 = Ps + (mw + mf * 16 + grp) * APAD + kc * 8;
                const unsigned* r1 = Ps + (mw + mf * 16 + grp + 8) * APAD + kc * 8;
                a[mf][0] = r0[t4];
                a[mf][1] = r1[t4];
                a[mf][2] = r0[t4 + 4];
                a[mf][3] = r1[t4 + 4];
            }
#pragma unroll
            for (int nc = 0; nc < 8; nc++) {
                unsigned b0 = Vs[(kc * 8 + t4)     * APAD + nc * 8 + grp];
                unsigned b1 = Vs[(kc * 8 + t4 + 4) * APAD + nc * 8 + grp];
                mma8(O[0][nc], a[0][0], a[0][1], a[0][2], a[0][3], b0, b1);
                mma8(O[1][nc], a[1][0], a[1][1], a[1][2], a[1][3], b0, b1);
            }
        }
    }

    // ---- epilogue: normalize, write to [B,T,C] ----
#pragma unroll
    for (int mf = 0; mf < 2; mf++) {
#pragma unroll
        for (int hh = 0; hh < 2; hh++) {
            float inv = 1.f / lrow[mf][hh];
            int row = q0 + mw + mf * 16 + hh * 8 + grp;
            size_t base = ((size_t)(b * SEQ + row)) * EMBD + h * HDIM;
#pragma unroll
            for (int nc = 0; nc < 8; nc++) {
                int c = nc * 8 + 2 * t4;
                *(float2*)(g_att + base + c) =
                    make_float2(O[mf][nc][2 * hh] * inv, O[mf][nc][2 * hh + 1] * inv);
            }
        }
    }
}

// ---------------- launcher ----------------
extern "C" void kernel_launch(void* const* d_in, const int* in_sizes, int n_in,
                              void* d_out, int out_size)
{
    const float* x     = (const float*)d_in[0];
    const float* Wqkv  = (const float*)d_in[1];
    const float* bqkv  = (const float*)d_in[2];
    const float* Wproj = (const float*)d_in[3];
    const float* bproj = (const float*)d_in[4];
    const float* cosb  = (const float*)d_in[5];
    const float* sinb  = (const float*)d_in[6];
    float* out = (float*)d_out;

    void *p_qkv = nullptr, *p_att = nullptr;
    cudaGetSymbolAddress(&p_qkv, g_qkv);
    cudaGetSymbolAddress(&p_att, g_att);

    // 1) QKV GEMM: [4096,1024] @ [1024,3072] + bias (tf32 tensor cores)
    gemm_tf32<<<dim3(QKVN / 128, BT / 128), 256>>>(
        x, Wqkv, bqkv, (float*)p_qkv, BT, QKVN, EMBD);

    // 2) RoPE + transpose to [B,H,T,D]
    rope_scatter<<<(BATCH * SEQ * NHEAD * (HDIM / 2)) / 256, 256>>>(cosb, sinb);

    // 3) causal flash attention (tf32 tensor cores, 128-row tiles)
    const int smem_bytes = 384 * APAD * sizeof(unsigned);   // 104448
    cudaFuncSetAttribute(attn_mma, cudaFuncAttributeMaxDynamicSharedMemorySize, smem_bytes);
    attn_mma<<<dim3(SEQ / 128, BATCH * NHEAD), 128, smem_bytes>>>();

    // 4) output projection: [4096,1024] @ [1024,1024] + bias (tf32 tensor cores)
    gemm_tf32<<<dim3(EMBD / 128, BT / 128), 256>>>(
        (const float*)p_att, Wproj, bproj, out, BT, EMBD, EMBD);
}

// round 4
// speedup vs baseline: 3.8866x; 1.3027x over previous
#include <cuda_runtime.h>
#include <cuda_fp16.h>
#include <math.h>

// Problem constants
#define BATCH 2
#define SEQ   2048
#define EMBD  1024
#define NHEAD 16
#define HDIM  64
#define BT    (BATCH*SEQ)          // 4096
#define QKVN  (3*EMBD)             // 3072
#define LOG2E 1.4426950408889634f

// ---------------- scratch (device globals) ----------------
__device__ float  g_qkv[BT * QKVN];                      // [B*T, 3C] f32
__device__ __half g_qh[BATCH * NHEAD * SEQ * HDIM];      // [bh][t][d]
__device__ __half g_kh[BATCH * NHEAD * SEQ * HDIM];      // [bh][t][d]
__device__ __half g_vt[BATCH * NHEAD * HDIM * SEQ];      // [bh][d][t]  (transposed!)
__device__ float  g_att[BT * EMBD];                      // [B,T,C] f32

// ---------------- helpers ----------------
__device__ __forceinline__ unsigned packh2(float a, float b) {
    __half2 h = __floats2half2_rn(a, b);
    return *(unsigned*)&h;
}

__device__ __forceinline__ void mma16(float* c,
    unsigned a0, unsigned a1, unsigned a2, unsigned a3,
    unsigned b0, unsigned b1)
{
    asm volatile(
        "mma.sync.aligned.m16n8k16.row.col.f32.f16.f16.f32 "
        "{%0,%1,%2,%3},{%4,%5,%6,%7},{%8,%9},{%0,%1,%2,%3};"
        : "+f"(c[0]), "+f"(c[1]), "+f"(c[2]), "+f"(c[3])
        : "r"(a0), "r"(a1), "r"(a2), "r"(a3), "r"(b0), "r"(b1));
}

// 2^t via FMA-pipe polynomial (no MUFU). Valid t <= ~0, clamps below -126.
__device__ __forceinline__ float exp2_poly(float t) {
    t = fmaxf(t, -126.0f);
    float z = t + 12582912.0f;               // 1.5*2^23: round-to-int
    int   ei = __float_as_int(z) - 0x4B400000;
    float f = t - (float)ei;                 // frac in [-0.5, 0.5]
    float p = 1.3333558e-3f;
    p = fmaf(p, f, 9.6181291e-3f);
    p = fmaf(p, f, 5.5504109e-2f);
    p = fmaf(p, f, 2.4022651e-1f);
    p = fmaf(p, f, 6.9314718e-1f);
    p = fmaf(p, f, 1.0f);
    return __int_as_float(__float_as_int(p) + (ei << 23));
}

__device__ __forceinline__ void cpa16(__half* dst_smem, const __half* src_gmem) {
    unsigned d = (unsigned)__cvta_generic_to_shared(dst_smem);
    asm volatile("cp.async.cg.shared.global [%0], [%1], 16;" :: "r"(d), "l"(src_gmem));
}
#define CP_COMMIT() asm volatile("cp.async.commit_group;")
#define CP_WAIT0()  asm volatile("cp.async.wait_group 0;" ::: "memory")
#define CP_WAIT1()  asm volatile("cp.async.wait_group 1;" ::: "memory")

// ---------------- fp16 tensor-core GEMM: C[M,N] = A[M,K]@B[K,N] + bias ----------------
// 256 threads = 8 warps; BM=128, BN=128, BK=32; warp computes 32x64.
#define GPH 40   // smem pitch (halfs) = 80B: conflict-free fragment loads
__global__ __launch_bounds__(256) void gemm_h(
    const float* __restrict__ A, const float* __restrict__ B,
    const float* __restrict__ bias, float* __restrict__ C,
    int M, int N, int K)
{
    __shared__ __half As[128 * GPH];   // [m][k]
    __shared__ __half Bs[128 * GPH];   // [n][k]  (B transposed)

    const int tid  = threadIdx.x;
    const int w    = tid >> 5;
    const int lane = tid & 31;
    const int grp  = lane >> 2;
    const int t4   = lane & 3;
    const int mw   = (w >> 1) * 32;
    const int nw   = (w & 1) * 64;
    const int m0   = blockIdx.y * 128;
    const int n0   = blockIdx.x * 128;

    float acc[2][8][4];
#pragma unroll
    for (int mf = 0; mf < 2; mf++)
#pragma unroll
        for (int nc = 0; nc < 8; nc++)
#pragma unroll
            for (int j = 0; j < 4; j++) acc[mf][nc][j] = 0.f;

    for (int k0 = 0; k0 < K; k0 += 32) {
        // stage A 128x32 -> half
#pragma unroll
        for (int it = 0; it < 4; it++) {
            int slot = tid + it * 256;        // 0..1023
            int ar = slot >> 3;
            int c4 = (slot & 7) << 2;
            float4 v = *(const float4*)(A + (size_t)(m0 + ar) * K + k0 + c4);
            uint2 u = make_uint2(packh2(v.x, v.y), packh2(v.z, v.w));
            *(uint2*)(As + ar * GPH + c4) = u;
        }
        // stage B 32x128 -> half, transposed to [n][k]
#pragma unroll
        for (int it = 0; it < 4; it++) {
            int slot = tid + it * 256;        // 0..1023
            int n  = slot & 127;
            int k4 = (slot >> 7) << 2;        // 0,4,...,28
            const float* bp = B + (size_t)(k0 + k4) * N + n0 + n;
            float b0 = bp[0];
            float b1 = bp[N];
            float b2 = bp[2 * N];
            float b3 = bp[3 * N];
            *(uint2*)(Bs + n * GPH + k4) = make_uint2(packh2(b0, b1), packh2(b2, b3));
        }
        __syncthreads();

#pragma unroll
        for (int ks = 0; ks < 32; ks += 16) {
            unsigned a[2][4];
#pragma unroll
            for (int mf = 0; mf < 2; mf++) {
                const __half* r0 = As + (mw + mf * 16 + grp) * GPH + ks;
                a[mf][0] = *(const unsigned*)(r0 + 2 * t4);
                a[mf][1] = *(const unsigned*)(r0 + 8 * GPH + 2 * t4);
                a[mf][2] = *(const unsigned*)(r0 + 2 * t4 + 8);
                a[mf][3] = *(const unsigned*)(r0 + 8 * GPH + 2 * t4 + 8);
            }
#pragma unroll
            for (int nc = 0; nc < 8; nc++) {
                const __half* br = Bs + (nw + nc * 8 + grp) * GPH + ks;
                unsigned b0 = *(const unsigned*)(br + 2 * t4);
                unsigned b1 = *(const unsigned*)(br + 2 * t4 + 8);
                mma16(acc[0][nc], a[0][0], a[0][1], a[0][2], a[0][3], b0, b1);
                mma16(acc[1][nc], a[1][0], a[1][1], a[1][2], a[1][3], b0, b1);
            }
        }
        __syncthreads();
    }

    // epilogue
#pragma unroll
    for (int mf = 0; mf < 2; mf++) {
#pragma unroll
        for (int hh = 0; hh < 2; hh++) {
            int m = m0 + mw + mf * 16 + hh * 8 + grp;
            float* crow = C + (size_t)m * N + n0 + nw;
#pragma unroll
            for (int nc = 0; nc < 8; nc++) {
                int c = nc * 8 + 2 * t4;
                float2 o;
                o.x = acc[mf][nc][2 * hh]     + bias[n0 + nw + c];
                o.y = acc[mf][nc][2 * hh + 1] + bias[n0 + nw + c + 1];
                *(float2*)(crow + c) = o;
            }
        }
    }
}

// ---------------- RoPE: qkv(f32) -> g_qh, g_kh (half, [bh][t][d]), g_vt (half, [bh][d][t]) ----
// block = (bh, 64-t tile); 256 threads
#define VSP 68
__global__ __launch_bounds__(256) void rope_h(
    const float* __restrict__ cosb, const float* __restrict__ sinb)
{
    __shared__ __half sv[64 * VSP];   // [d][t_local]

    const int tt = blockIdx.x;        // t tile (64)
    const int bh = blockIdx.y;
    const int b  = bh >> 4;
    const int h  = bh & 15;
    const int tid = threadIdx.x;

    // phase A: rope q,k -> global; v -> smem transposed
#pragma unroll
    for (int it = 0; it < 8; it++) {
        int slot = tid + it * 256;        // 0..2047
        int i  = slot & 31;               // pair index
        int tr = slot >> 5;               // 0..63
        int t  = tt * 64 + tr;

        float c = cosb[t * 32 + i];
        float s = sinb[t * 32 + i];

        size_t rowq = ((size_t)(b * SEQ + t)) * QKVN + h * HDIM + 2 * i;
        float2 q = *(const float2*)(g_qkv + rowq);
        float2 k = *(const float2*)(g_qkv + rowq + EMBD);
        float2 v = *(const float2*)(g_qkv + rowq + 2 * EMBD);

        size_t o = ((size_t)(bh * SEQ + t)) * HDIM + 2 * i;
        *(unsigned*)(g_qh + o) = packh2(q.x * c - q.y * s, q.x * s + q.y * c);
        *(unsigned*)(g_kh + o) = packh2(k.x * c - k.y * s, k.x * s + k.y * c);
        sv[(2 * i) * VSP + tr]     = __float2half(v.x);
        sv[(2 * i + 1) * VSP + tr] = __float2half(v.y);
    }
    __syncthreads();

    // phase B: write Vt rows coalesced
#pragma unroll
    for (int it = 0; it < 4; it++) {
        int slot = tid + it * 256;        // 0..1023
        int d  = slot >> 4;               // 0..63
        int c4 = (slot & 15) << 2;        // 0..60
        uint2 u = *(const uint2*)(sv + d * VSP + c4);
        *(uint2*)(g_vt + ((size_t)(bh * HDIM + d)) * SEQ + tt * 64 + c4) = u;
    }
}

// ---------------- flash attention, fp16 mma, register-resident P, causal ----------------
// 128 threads = 4 warps; CTA = 128 query rows; warp w owns rows 32w..32w+31.
// 64-key tiles, double-buffered cp.async staging. Pitch 72 halfs: conflict-free frags.
#define AP 72
__global__ __launch_bounds__(128) void attn_h()
{
    extern __shared__ __half sm[];
    __half* Qs = sm;                         // 128*72
    __half* Kb0 = sm + 128 * AP;             // 2 x 64*72
    __half* Vb0 = sm + 128 * AP + 2 * 64 * AP;

    const int qt = (int)gridDim.x - 1 - (int)blockIdx.x;  // long blocks first
    const int bh = blockIdx.y;
    const int b  = bh >> 4;
    const int h  = bh & 15;
    const __half* qp = g_qh + (size_t)bh * SEQ * HDIM;
    const __half* kp = g_kh + (size_t)bh * SEQ * HDIM;
    const __half* vp = g_vt + (size_t)bh * HDIM * SEQ;   // [d][t]
    const int q0 = qt * 128;

    const int tid  = threadIdx.x;
    const int w    = tid >> 5;
    const int lane = tid & 31;
    const int grp  = lane >> 2;
    const int t4   = lane & 3;
    const int mw   = w * 32;

    // prologue: stage Q (128x64) + tile 0 (K,V) via cp.async
#pragma unroll
    for (int it = 0; it < 8; it++) {
        int slot = tid + it * 128;          // 0..1023
        int r  = slot >> 3;
        int c8 = (slot & 7) << 3;
        cpa16(Qs + r * AP + c8, qp + (size_t)(q0 + r) * HDIM + c8);
    }
#pragma unroll
    for (int it = 0; it < 4; it++) {
        int slot = tid + it * 128;          // 0..511
        int r  = slot >> 3;
        int c8 = (slot & 7) << 3;
        cpa16(Kb0 + r * AP + c8, kp + (size_t)r * HDIM + c8);
        cpa16(Vb0 + r * AP + c8, vp + (size_t)r * SEQ + c8);
    }
    CP_COMMIT();

    float O[2][8][4];
#pragma unroll
    for (int mf = 0; mf < 2; mf++)
#pragma unroll
        for (int nc = 0; nc < 8; nc++)
#pragma unroll
            for (int j = 0; j < 4; j++) O[mf][nc][j] = 0.f;
    float mrow[2][2], lrow[2][2];
#pragma unroll
    for (int mf = 0; mf < 2; mf++)
#pragma unroll
        for (int hh = 0; hh < 2; hh++) { mrow[mf][hh] = -INFINITY; lrow[mf][hh] = 0.f; }

    const int kt_max = 2 * qt + 1;
    for (int kt = 0; kt <= kt_max; kt++) {
        const int k0 = kt * 64;
        // prefetch next tile
        if (kt < kt_max) {
            const int kn = k0 + 64;
            __half* Kn = Kb0 + ((kt + 1) & 1) * 64 * AP;
            __half* Vn = Vb0 + ((kt + 1) & 1) * 64 * AP;
#pragma unroll
            for (int it = 0; it < 4; it++) {
                int slot = tid + it * 128;
                int r  = slot >> 3;
                int c8 = (slot & 7) << 3;
                cpa16(Kn + r * AP + c8, kp + (size_t)(kn + r) * HDIM + c8);
                cpa16(Vn + r * AP + c8, vp + (size_t)r * SEQ + kn + c8);
            }
            CP_COMMIT();
            CP_WAIT1();
        } else {
            CP_WAIT0();
        }
        __syncthreads();

        // per-warp skip of fully-masked tiles
        if (k0 <= q0 + mw + 31) {
            const __half* Kb = Kb0 + (kt & 1) * 64 * AP;
            const __half* Vb = Vb0 + (kt & 1) * 64 * AP;

            // ---- S = Q K^T ----
            float S[2][8][4];
#pragma unroll
            for (int mf = 0; mf < 2; mf++)
#pragma unroll
                for (int nc = 0; nc < 8; nc++)
#pragma unroll
                    for (int j = 0; j < 4; j++) S[mf][nc][j] = 0.f;

#pragma unroll
            for (int ks = 0; ks < 4; ks++) {
                unsigned a[2][4];
#pragma unroll
                for (int mf = 0; mf < 2; mf++) {
                    const __half* r0 = Qs + (mw + mf * 16 + grp) * AP + ks * 16;
                    a[mf][0] = *(const unsigned*)(r0 + 2 * t4);
                    a[mf][1] = *(const unsigned*)(r0 + 8 * AP + 2 * t4);
                    a[mf][2] = *(const unsigned*)(r0 + 2 * t4 + 8);
                    a[mf][3] = *(const unsigned*)(r0 + 8 * AP + 2 * t4 + 8);
                }
#pragma unroll
                for (int nc = 0; nc < 8; nc++) {
                    const __half* kr = Kb + (nc * 8 + grp) * AP + ks * 16;
                    unsigned b0 = *(const unsigned*)(kr + 2 * t4);
                    unsigned b1 = *(const unsigned*)(kr + 2 * t4 + 8);
                    mma16(S[0][nc], a[0][0], a[0][1], a[0][2], a[0][3], b0, b1);
                    mma16(S[1][nc], a[1][0], a[1][1], a[1][2], a[1][3], b0, b1);
                }
            }

            // ---- causal mask (raw S domain) ----
            const bool need_mask = (k0 + 63 > q0 + mw);
            if (need_mask) {
#pragma unroll
                for (int mf = 0; mf < 2; mf++) {
                    int r0g = q0 + mw + mf * 16 + grp;
                    int r1g = r0g + 8;
#pragma unroll
                    for (int nc = 0; nc < 8; nc++) {
                        int col = k0 + nc * 8 + 2 * t4;
                        if (col     > r0g) S[mf][nc][0] = -INFINITY;
                        if (col + 1 > r0g) S[mf][nc][1] = -INFINITY;
                        if (col     > r1g) S[mf][nc][2] = -INFINITY;
                        if (col + 1 > r1g) S[mf][nc][3] = -INFINITY;
                    }
                }
            }

            // ---- online softmax: P = exp2(S*0.125*log2e - m*log2e), FMA-pipe poly ----
#pragma unroll
            for (int mf = 0; mf < 2; mf++) {
#pragma unroll
                for (int hh = 0; hh < 2; hh++) {
                    float mx = -INFINITY;
#pragma unroll
                    for (int nc = 0; nc < 8; nc++)
                        mx = fmaxf(mx, fmaxf(S[mf][nc][2 * hh], S[mf][nc][2 * hh + 1]));
                    mx = fmaxf(mx, __shfl_xor_sync(0xffffffffu, mx, 1));
                    mx = fmaxf(mx, __shfl_xor_sync(0xffffffffu, mx, 2));
                    mx *= 0.125f;

                    float mold = mrow[mf][hh];
                    float mnew = fmaxf(mold, mx);
                    float al   = exp2_poly((mold - mnew) * LOG2E);
                    mrow[mf][hh] = mnew;
                    float mb = mnew * LOG2E;

                    float sum = 0.f;
#pragma unroll
                    for (int nc = 0; nc < 8; nc++) {
                        float p0 = exp2_poly(fmaf(S[mf][nc][2 * hh],     0.1803368801f, -mb));
                        float p1 = exp2_poly(fmaf(S[mf][nc][2 * hh + 1], 0.1803368801f, -mb));
                        S[mf][nc][2 * hh]     = p0;
                        S[mf][nc][2 * hh + 1] = p1;
                        sum += p0 + p1;
                    }
                    sum += __shfl_xor_sync(0xffffffffu, sum, 1);
                    sum += __shfl_xor_sync(0xffffffffu, sum, 2);
                    lrow[mf][hh] = lrow[mf][hh] * al + sum;

#pragma unroll
                    for (int nc = 0; nc < 8; nc++) {
                        O[mf][nc][2 * hh]     *= al;
                        O[mf][nc][2 * hh + 1] *= al;
                    }
                }
            }

            // ---- O += P V : P lives in registers as A-fragments ----
#pragma unroll
            for (int ks = 0; ks < 4; ks++) {
                unsigned a[2][4];
#pragma unroll
                for (int mf = 0; mf < 2; mf++) {
                    a[mf][0] = packh2(S[mf][2 * ks][0],     S[mf][2 * ks][1]);
                    a[mf][1] = packh2(S[mf][2 * ks][2],     S[mf][2 * ks][3]);
                    a[mf][2] = packh2(S[mf][2 * ks + 1][0], S[mf][2 * ks + 1][1]);
                    a[mf][3] = packh2(S[mf][2 * ks + 1][2], S[mf][2 * ks + 1][3]);
                }
#pragma unroll
                for (int nc = 0; nc < 8; nc++) {
                    const __half* vr = Vb + (nc * 8 + grp) * AP + ks * 16;
                    unsigned b0 = *(const unsigned*)(vr + 2 * t4);
                    unsigned b1 = *(const unsigned*)(vr + 2 * t4 + 8);
                    mma16(O[0][nc], a[0][0], a[0][1], a[0][2], a[0][3], b0, b1);
                    mma16(O[1][nc], a[1][0], a[1][1], a[1][2], a[1][3], b0, b1);
                }
            }
        }
        __syncthreads();
    }

    // ---- epilogue: normalize, write to [B,T,C] f32 ----
#pragma unroll
    for (int mf = 0; mf < 2; mf++) {
#pragma unroll
        for (int hh = 0; hh < 2; hh++) {
            float inv = 1.f / lrow[mf][hh];
            int row = q0 + mw + mf * 16 + hh * 8 + grp;
            size_t base = ((size_t)(b * SEQ + row)) * EMBD + h * HDIM;
#pragma unroll
            for (int nc = 0; nc < 8; nc++) {
                int c = nc * 8 + 2 * t4;
                *(float2*)(g_att + base + c) =
                    make_float2(O[mf][nc][2 * hh] * inv, O[mf][nc][2 * hh + 1] * inv);
            }
        }
    }
}

// ---------------- launcher ----------------
extern "C" void kernel_launch(void* const* d_in, const int* in_sizes, int n_in,
                              void* d_out, int out_size)
{
    const float* x     = (const float*)d_in[0];
    const float* Wqkv  = (const float*)d_in[1];
    const float* bqkv  = (const float*)d_in[2];
    const float* Wproj = (const float*)d_in[3];
    const float* bproj = (const float*)d_in[4];
    const float* cosb  = (const float*)d_in[5];
    const float* sinb  = (const float*)d_in[6];
    float* out = (float*)d_out;

    void *p_qkv = nullptr, *p_att = nullptr;
    cudaGetSymbolAddress(&p_qkv, g_qkv);
    cudaGetSymbolAddress(&p_att, g_att);

    // 1) QKV GEMM (fp16 tensor cores)
    gemm_h<<<dim3(QKVN / 128, BT / 128), 256>>>(
        x, Wqkv, bqkv, (float*)p_qkv, BT, QKVN, EMBD);

    // 2) RoPE -> half Q/K + transposed half V
    rope_h<<<dim3(SEQ / 64, BATCH * NHEAD), 256>>>(cosb, sinb);

    // 3) causal flash attention (fp16 mma, register P, cp.async pipeline)
    const int smem_bytes = (128 * AP + 4 * 64 * AP) * sizeof(__half);   // 55296
    cudaFuncSetAttribute(attn_h, cudaFuncAttributeMaxDynamicSharedMemorySize, smem_bytes);
    attn_h<<<dim3(SEQ / 128, BATCH * NHEAD), 128, smem_bytes>>>();

    // 4) output projection (fp16 tensor cores)
    gemm_h<<<dim3(EMBD / 128, BT / 128), 256>>>(
        (const float*)p_att, Wproj, bproj, out, BT, EMBD, EMBD);
}

// round 5
// speedup vs baseline: 5.3707x; 1.3819x over previous
#include <cuda_runtime.h>
#include <cuda_fp16.h>
#include <math.h>

// Problem constants
#define BATCH 2
#define SEQ   2048
#define EMBD  1024
#define NHEAD 16
#define HDIM  64
#define BT    (BATCH*SEQ)          // 4096
#define QKVN  (3*EMBD)             // 3072
#define LOG2E 1.4426950408889634f

// ---------------- scratch (device globals) ----------------
__device__ __half g_xh[BT * EMBD];                       // x in half
__device__ __half g_wqkvt[QKVN * EMBD];                  // Wqkv^T [3072][1024] half
__device__ __half g_wprojt[EMBD * EMBD];                 // Wproj^T [1024][1024] half
__device__ float  g_qkv[BT * QKVN];                      // [B*T, 3C] f32
__device__ __half g_qh[BATCH * NHEAD * SEQ * HDIM];      // [bh][t][d]
__device__ __half g_kh[BATCH * NHEAD * SEQ * HDIM];      // [bh][t][d]
__device__ __half g_vt[BATCH * NHEAD * HDIM * SEQ];      // [bh][d][t]
__device__ __half g_atth[BT * EMBD];                     // attention out, half

// ---------------- helpers ----------------
__device__ __forceinline__ unsigned packh2(float a, float b) {
    __half2 h = __floats2half2_rn(a, b);
    return *(unsigned*)&h;
}

__device__ __forceinline__ void mma16(float* c,
    unsigned a0, unsigned a1, unsigned a2, unsigned a3,
    unsigned b0, unsigned b1)
{
    asm volatile(
        "mma.sync.aligned.m16n8k16.row.col.f32.f16.f16.f32 "
        "{%0,%1,%2,%3},{%4,%5,%6,%7},{%8,%9},{%0,%1,%2,%3};"
        : "+f"(c[0]), "+f"(c[1]), "+f"(c[2]), "+f"(c[3])
        : "r"(a0), "r"(a1), "r"(a2), "r"(a3), "r"(b0), "r"(b1));
}

// 2^t via FMA-pipe polynomial (no MUFU).
__device__ __forceinline__ float exp2_poly(float t) {
    t = fmaxf(t, -126.0f);
    float z = t + 12582912.0f;
    int   ei = __float_as_int(z) - 0x4B400000;
    float f = t - (float)ei;
    float p = 1.3333558e-3f;
    p = fmaf(p, f, 9.6181291e-3f);
    p = fmaf(p, f, 5.5504109e-2f);
    p = fmaf(p, f, 2.4022651e-1f);
    p = fmaf(p, f, 6.9314718e-1f);
    p = fmaf(p, f, 1.0f);
    return __int_as_float(__float_as_int(p) + (ei << 23));
}

__device__ __forceinline__ void cpa16(__half* dst_smem, const __half* src_gmem) {
    unsigned d = (unsigned)__cvta_generic_to_shared(dst_smem);
    asm volatile("cp.async.cg.shared.global [%0], [%1], 16;" :: "r"(d), "l"(src_gmem));
}
#define CP_COMMIT() asm volatile("cp.async.commit_group;")
#define CP_WAIT0()  asm volatile("cp.async.wait_group 0;" ::: "memory")
#define CP_WAIT1()  asm volatile("cp.async.wait_group 1;" ::: "memory")

// ---------------- f32 -> half elementwise (x) ----------------
__global__ __launch_bounds__(256) void conv_h(const float* __restrict__ in,
                                              __half* __restrict__ out)
{
    int i = blockIdx.x * 256 + threadIdx.x;      // one float4 per thread
    float4 v = *(const float4*)(in + (size_t)i * 4);
    *(uint2*)(out + (size_t)i * 4) = make_uint2(packh2(v.x, v.y), packh2(v.z, v.w));
}

// ---------------- transpose+convert: in[K][N] f32 -> out[N][K] half ----------------
__global__ __launch_bounds__(256) void transp_h(const float* __restrict__ in,
                                                __half* __restrict__ out,
                                                int K, int N)
{
    __shared__ __half tile[32][33];
    const int n0 = blockIdx.x * 32;
    const int k0 = blockIdx.y * 32;
    const int tx = threadIdx.x & 31;
    const int ty = threadIdx.x >> 5;     // 0..7
#pragma unroll
    for (int j = 0; j < 4; j++) {
        int kr = ty + j * 8;
        tile[kr][tx] = __float2half(in[(size_t)(k0 + kr) * N + n0 + tx]);
    }
    __syncthreads();
#pragma unroll
    for (int j = 0; j < 4; j++) {
        int nr = ty + j * 8;
        out[(size_t)(n0 + nr) * K + k0 + tx] = tile[tx][nr];
    }
}

// ---------------- fp16 GEMM, half A [M][K], half Bt [N][K], f32 C + bias ----------------
// 256 threads = 8 warps; BM=128, BN=128, BK=32; warp computes 32x64.
// Double-buffered cp.async staging.
#define GPH 40
__global__ __launch_bounds__(256) void gemm_hh(
    const __half* __restrict__ A, const __half* __restrict__ Bt,
    const float* __restrict__ bias, float* __restrict__ C,
    int M, int N, int K)
{
    __shared__ __half As[2][128 * GPH];   // [m][k]
    __shared__ __half Bs[2][128 * GPH];   // [n][k]

    const int tid  = threadIdx.x;
    const int w    = tid >> 5;
    const int lane = tid & 31;
    const int grp  = lane >> 2;
    const int t4   = lane & 3;
    const int mw   = (w >> 1) * 32;
    const int nw   = (w & 1) * 64;
    const int m0   = blockIdx.y * 128;
    const int n0   = blockIdx.x * 128;

    // staging map: 512 chunks each for A and B; thread does 2 of each
    const int cr0 = tid >> 1;                   // rows tid/2 and +128... recompute below

    float acc[2][8][4];
#pragma unroll
    for (int mf = 0; mf < 2; mf++)
#pragma unroll
        for (int nc = 0; nc < 8; nc++)
#pragma unroll
            for (int j = 0; j < 4; j++) acc[mf][nc][j] = 0.f;

    const int nk = K / 32;

    // prologue: stage tile 0
#pragma unroll
    for (int it = 0; it < 2; it++) {
        int c = tid + it * 256;          // 0..511
        int r = c >> 2;
        int o8 = (c & 3) << 3;
        cpa16(As[0] + r * GPH + o8, A + (size_t)(m0 + r) * K + o8);
        cpa16(Bs[0] + r * GPH + o8, Bt + (size_t)(n0 + r) * K + o8);
    }
    CP_COMMIT();

    for (int i = 0; i < nk; i++) {
        if (i + 1 < nk) {
            const int kn = (i + 1) * 32;
            __half* An = As[(i + 1) & 1];
            __half* Bn = Bs[(i + 1) & 1];
#pragma unroll
            for (int it = 0; it < 2; it++) {
                int c = tid + it * 256;
                int r = c >> 2;
                int o8 = (c & 3) << 3;
                cpa16(An + r * GPH + o8, A + (size_t)(m0 + r) * K + kn + o8);
                cpa16(Bn + r * GPH + o8, Bt + (size_t)(n0 + r) * K + kn + o8);
            }
            CP_COMMIT();
            CP_WAIT1();
        } else {
            CP_WAIT0();
        }
        __syncthreads();

        const __half* Ac = As[i & 1];
        const __half* Bc = Bs[i & 1];
#pragma unroll
        for (int ks = 0; ks < 32; ks += 16) {
            unsigned a[2][4];
#pragma unroll
            for (int mf = 0; mf < 2; mf++) {
                const __half* r0 = Ac + (mw + mf * 16 + grp) * GPH + ks;
                a[mf][0] = *(const unsigned*)(r0 + 2 * t4);
                a[mf][1] = *(const unsigned*)(r0 + 8 * GPH + 2 * t4);
                a[mf][2] = *(const unsigned*)(r0 + 2 * t4 + 8);
                a[mf][3] = *(const unsigned*)(r0 + 8 * GPH + 2 * t4 + 8);
            }
#pragma unroll
            for (int nc = 0; nc < 8; nc++) {
                const __half* br = Bc + (nw + nc * 8 + grp) * GPH + ks;
                unsigned b0 = *(const unsigned*)(br + 2 * t4);
                unsigned b1 = *(const unsigned*)(br + 2 * t4 + 8);
                mma16(acc[0][nc], a[0][0], a[0][1], a[0][2], a[0][3], b0, b1);
                mma16(acc[1][nc], a[1][0], a[1][1], a[1][2], a[1][3], b0, b1);
            }
        }
        __syncthreads();
    }

    // epilogue
#pragma unroll
    for (int mf = 0; mf < 2; mf++) {
#pragma unroll
        for (int hh = 0; hh < 2; hh++) {
            int m = m0 + mw + mf * 16 + hh * 8 + grp;
            float* crow = C + (size_t)m * N + n0 + nw;
#pragma unroll
            for (int nc = 0; nc < 8; nc++) {
                int c = nc * 8 + 2 * t4;
                float2 o;
                o.x = acc[mf][nc][2 * hh]     + bias[n0 + nw + c];
                o.y = acc[mf][nc][2 * hh + 1] + bias[n0 + nw + c + 1];
                *(float2*)(crow + c) = o;
            }
        }
    }
}

// ---------------- proj GEMM with half A: same but writes f32 out ------
// (gemm_hh covers both; proj A is g_atth)

// ---------------- RoPE: qkv(f32) -> half q,k ([bh][t][d]) + half v transposed ----------------
#define VSP 68
__global__ __launch_bounds__(256) void rope_h(
    const float* __restrict__ cosb, const float* __restrict__ sinb)
{
    __shared__ __half sv[64 * VSP];

    const int tt = blockIdx.x;
    const int bh = blockIdx.y;
    const int b  = bh >> 4;
    const int h  = bh & 15;
    const int tid = threadIdx.x;

#pragma unroll
    for (int it = 0; it < 8; it++) {
        int slot = tid + it * 256;
        int i  = slot & 31;
        int tr = slot >> 5;
        int t  = tt * 64 + tr;

        float c = cosb[t * 32 + i];
        float s = sinb[t * 32 + i];

        size_t rowq = ((size_t)(b * SEQ + t)) * QKVN + h * HDIM + 2 * i;
        float2 q = *(const float2*)(g_qkv + rowq);
        float2 k = *(const float2*)(g_qkv + rowq + EMBD);
        float2 v = *(const float2*)(g_qkv + rowq + 2 * EMBD);

        size_t o = ((size_t)(bh * SEQ + t)) * HDIM + 2 * i;
        *(unsigned*)(g_qh + o) = packh2(q.x * c - q.y * s, q.x * s + q.y * c);
        *(unsigned*)(g_kh + o) = packh2(k.x * c - k.y * s, k.x * s + k.y * c);
        sv[(2 * i) * VSP + tr]     = __float2half(v.x);
        sv[(2 * i + 1) * VSP + tr] = __float2half(v.y);
    }
    __syncthreads();

#pragma unroll
    for (int it = 0; it < 4; it++) {
        int slot = tid + it * 256;
        int d  = slot >> 4;
        int c4 = (slot & 15) << 2;
        uint2 u = *(const uint2*)(sv + d * VSP + c4);
        *(uint2*)(g_vt + ((size_t)(bh * HDIM + d)) * SEQ + tt * 64 + c4) = u;
    }
}

// ---------------- flash attention: 256 thr = 8 warps x 16 rows, fp16 mma ----------------
#define AP 72
__global__ __launch_bounds__(256) void attn_h()
{
    extern __shared__ __half sm[];
    __half* Qs  = sm;                        // 128*72
    __half* Kb0 = sm + 128 * AP;             // 2 x 64*72
    __half* Vb0 = sm + 128 * AP + 2 * 64 * AP;

    const int qt = (int)gridDim.x - 1 - (int)blockIdx.x;
    const int bh = blockIdx.y;
    const int b  = bh >> 4;
    const int h  = bh & 15;
    const __half* qp = g_qh + (size_t)bh * SEQ * HDIM;
    const __half* kp = g_kh + (size_t)bh * SEQ * HDIM;
    const __half* vp = g_vt + (size_t)bh * HDIM * SEQ;
    const int q0 = qt * 128;

    const int tid  = threadIdx.x;
    const int w    = tid >> 5;
    const int lane = tid & 31;
    const int grp  = lane >> 2;
    const int t4   = lane & 3;
    const int mw   = w * 16;                 // warp owns rows mw..mw+15

    // prologue: stage Q + tile 0 K/V
#pragma unroll
    for (int it = 0; it < 4; it++) {
        int slot = tid + it * 256;           // 0..1023
        int r  = slot >> 3;
        int c8 = (slot & 7) << 3;
        cpa16(Qs + r * AP + c8, qp + (size_t)(q0 + r) * HDIM + c8);
    }
#pragma unroll
    for (int it = 0; it < 2; it++) {
        int slot = tid + it * 256;           // 0..511
        int r  = slot >> 3;
        int c8 = (slot & 7) << 3;
        cpa16(Kb0 + r * AP + c8, kp + (size_t)r * HDIM + c8);
        cpa16(Vb0 + r * AP + c8, vp + (size_t)r * SEQ + c8);
    }
    CP_COMMIT();

    float O[8][4];
#pragma unroll
    for (int nc = 0; nc < 8; nc++)
#pragma unroll
        for (int j = 0; j < 4; j++) O[nc][j] = 0.f;
    float mrow[2] = {-INFINITY, -INFINITY};
    float lrow[2] = {0.f, 0.f};

    const int kt_max = 2 * qt + 1;
    for (int kt = 0; kt <= kt_max; kt++) {
        const int k0 = kt * 64;
        if (kt < kt_max) {
            const int kn = k0 + 64;
            __half* Kn = Kb0 + ((kt + 1) & 1) * 64 * AP;
            __half* Vn = Vb0 + ((kt + 1) & 1) * 64 * AP;
#pragma unroll
            for (int it = 0; it < 2; it++) {
                int slot = tid + it * 256;
                int r  = slot >> 3;
                int c8 = (slot & 7) << 3;
                cpa16(Kn + r * AP + c8, kp + (size_t)(kn + r) * HDIM + c8);
                cpa16(Vn + r * AP + c8, vp + (size_t)r * SEQ + kn + c8);
            }
            CP_COMMIT();
            CP_WAIT1();
        } else {
            CP_WAIT0();
        }
        __syncthreads();

        // per-warp tile skip (fully masked for this warp's 16 rows)
        if (k0 <= q0 + mw + 15) {
            const __half* Kb = Kb0 + (kt & 1) * 64 * AP;
            const __half* Vb = Vb0 + (kt & 1) * 64 * AP;

            // ---- S = Q K^T ----
            float S[8][4];
#pragma unroll
            for (int nc = 0; nc < 8; nc++)
#pragma unroll
                for (int j = 0; j < 4; j++) S[nc][j] = 0.f;

#pragma unroll
            for (int ks = 0; ks < 4; ks++) {
                const __half* r0 = Qs + (mw + grp) * AP + ks * 16;
                unsigned a0 = *(const unsigned*)(r0 + 2 * t4);
                unsigned a1 = *(const unsigned*)(r0 + 8 * AP + 2 * t4);
                unsigned a2 = *(const unsigned*)(r0 + 2 * t4 + 8);
                unsigned a3 = *(const unsigned*)(r0 + 8 * AP + 2 * t4 + 8);
#pragma unroll
                for (int nc = 0; nc < 8; nc++) {
                    const __half* kr = Kb + (nc * 8 + grp) * AP + ks * 16;
                    unsigned b0 = *(const unsigned*)(kr + 2 * t4);
                    unsigned b1 = *(const unsigned*)(kr + 2 * t4 + 8);
                    mma16(S[nc], a0, a1, a2, a3, b0, b1);
                }
            }

            // ---- causal mask ----
            if (k0 + 63 > q0 + mw) {
                int r0g = q0 + mw + grp;
                int r1g = r0g + 8;
#pragma unroll
                for (int nc = 0; nc < 8; nc++) {
                    int col = k0 + nc * 8 + 2 * t4;
                    if (col     > r0g) S[nc][0] = -INFINITY;
                    if (col + 1 > r0g) S[nc][1] = -INFINITY;
                    if (col     > r1g) S[nc][2] = -INFINITY;
                    if (col + 1 > r1g) S[nc][3] = -INFINITY;
                }
            }

            // ---- online softmax (FMA-pipe exp2) ----
#pragma unroll
            for (int hh = 0; hh < 2; hh++) {
                float mx = -INFINITY;
#pragma unroll
                for (int nc = 0; nc < 8; nc++)
                    mx = fmaxf(mx, fmaxf(S[nc][2 * hh], S[nc][2 * hh + 1]));
                mx = fmaxf(mx, __shfl_xor_sync(0xffffffffu, mx, 1));
                mx = fmaxf(mx, __shfl_xor_sync(0xffffffffu, mx, 2));
                mx *= 0.125f;

                float mold = mrow[hh];
                float mnew = fmaxf(mold, mx);
                float al   = exp2_poly((mold - mnew) * LOG2E);
                mrow[hh] = mnew;
                float mb = mnew * LOG2E;

                float sum = 0.f;
#pragma unroll
                for (int nc = 0; nc < 8; nc++) {
                    float p0 = exp2_poly(fmaf(S[nc][2 * hh],     0.1803368801f, -mb));
                    float p1 = exp2_poly(fmaf(S[nc][2 * hh + 1], 0.1803368801f, -mb));
                    S[nc][2 * hh]     = p0;
                    S[nc][2 * hh + 1] = p1;
                    sum += p0 + p1;
                }
                sum += __shfl_xor_sync(0xffffffffu, sum, 1);
                sum += __shfl_xor_sync(0xffffffffu, sum, 2);
                lrow[hh] = lrow[hh] * al + sum;

#pragma unroll
                for (int nc = 0; nc < 8; nc++) {
                    O[nc][2 * hh]     *= al;
                    O[nc][2 * hh + 1] *= al;
                }
            }

            // ---- O += P V (P register-resident as A-fragments) ----
#pragma unroll
            for (int ks = 0; ks < 4; ks++) {
                unsigned a0 = packh2(S[2 * ks][0],     S[2 * ks][1]);
                unsigned a1 = packh2(S[2 * ks][2],     S[2 * ks][3]);
                unsigned a2 = packh2(S[2 * ks + 1][0], S[2 * ks + 1][1]);
                unsigned a3 = packh2(S[2 * ks + 1][2], S[2 * ks + 1][3]);
#pragma unroll
                for (int nc = 0; nc < 8; nc++) {
                    const __half* vr = Vb + (nc * 8 + grp) * AP + ks * 16;
                    unsigned b0 = *(const unsigned*)(vr + 2 * t4);
                    unsigned b1 = *(const unsigned*)(vr + 2 * t4 + 8);
                    mma16(O[nc], a0, a1, a2, a3, b0, b1);
                }
            }
        }
        __syncthreads();
    }

    // ---- epilogue: normalize, write half to g_atth [B,T,C] ----
#pragma unroll
    for (int hh = 0; hh < 2; hh++) {
        float inv = 1.f / lrow[hh];
        int row = q0 + mw + hh * 8 + grp;
        size_t base = ((size_t)(b * SEQ + row)) * EMBD + h * HDIM;
#pragma unroll
        for (int nc = 0; nc < 8; nc++) {
            int c = nc * 8 + 2 * t4;
            *(unsigned*)(g_atth + base + c) =
                packh2(O[nc][2 * hh] * inv, O[nc][2 * hh + 1] * inv);
        }
    }
}

// ---------------- launcher ----------------
extern "C" void kernel_launch(void* const* d_in, const int* in_sizes, int n_in,
                              void* d_out, int out_size)
{
    const float* x     = (const float*)d_in[0];
    const float* Wqkv  = (const float*)d_in[1];
    const float* bqkv  = (const float*)d_in[2];
    const float* Wproj = (const float*)d_in[3];
    const float* bproj = (const float*)d_in[4];
    const float* cosb  = (const float*)d_in[5];
    const float* sinb  = (const float*)d_in[6];
    float* out = (float*)d_out;

    void *p_xh, *p_wqkvt, *p_wprojt, *p_qkv, *p_atth;
    cudaGetSymbolAddress(&p_xh, g_xh);
    cudaGetSymbolAddress(&p_wqkvt, g_wqkvt);
    cudaGetSymbolAddress(&p_wprojt, g_wprojt);
    cudaGetSymbolAddress(&p_qkv, g_qkv);
    cudaGetSymbolAddress(&p_atth, g_atth);

    // 0) pre-convert / pre-transpose
    conv_h<<<(BT * EMBD) / (256 * 4), 256>>>(x, (__half*)p_xh);
    transp_h<<<dim3(QKVN / 32, EMBD / 32), 256>>>(Wqkv, (__half*)p_wqkvt, EMBD, QKVN);
    transp_h<<<dim3(EMBD / 32, EMBD / 32), 256>>>(Wproj, (__half*)p_wprojt, EMBD, EMBD);

    // 1) QKV GEMM (half x half^T -> f32)
    gemm_hh<<<dim3(QKVN / 128, BT / 128), 256>>>(
        (const __half*)p_xh, (const __half*)p_wqkvt, bqkv, (float*)p_qkv,
        BT, QKVN, EMBD);

    // 2) RoPE -> half Q/K + transposed half V
    rope_h<<<dim3(SEQ / 64, BATCH * NHEAD), 256>>>(cosb, sinb);

    // 3) causal flash attention
    const int smem_bytes = (128 * AP + 4 * 64 * AP) * sizeof(__half);   // 55296
    cudaFuncSetAttribute(attn_h, cudaFuncAttributeMaxDynamicSharedMemorySize, smem_bytes);
    attn_h<<<dim3(SEQ / 128, BATCH * NHEAD), 256, smem_bytes>>>();

    // 4) output projection (half att x half^T -> f32 out)
    gemm_hh<<<dim3(EMBD / 128, BT / 128), 256>>>(
        (const __half*)p_atth, (const __half*)p_wprojt, bproj, out,
        BT, EMBD, EMBD);
}

// round 6
// speedup vs baseline: 6.2425x; 1.1623x over previous
#include <cuda_runtime.h>
#include <cuda_fp16.h>
#include <math.h>

// Problem constants
#define BATCH 2
#define SEQ   2048
#define EMBD  1024
#define NHEAD 16
#define HDIM  64
#define BT    (BATCH*SEQ)          // 4096
#define QKVN  (3*EMBD)             // 3072
#define LOG2E 1.4426950408889634f

// ---------------- scratch (device globals) ----------------
__device__ __half g_xh[BT * EMBD];                       // x in half
__device__ __half g_wqkvt[QKVN * EMBD];                  // Wqkv^T [3072][1024] half
__device__ __half g_wprojt[EMBD * EMBD];                 // Wproj^T [1024][1024] half
__device__ __half g_qh[BATCH * NHEAD * SEQ * HDIM];      // [bh][t][d]
__device__ __half g_kh[BATCH * NHEAD * SEQ * HDIM];      // [bh][t][d]
__device__ __half g_vh[BATCH * NHEAD * SEQ * HDIM];      // [bh][t][d]
__device__ __half g_vt[BATCH * NHEAD * HDIM * SEQ];      // [bh][d][t]
__device__ __half g_atth[BT * EMBD];                     // attention out, half

// ---------------- helpers ----------------
__device__ __forceinline__ unsigned packh2(float a, float b) {
    __half2 h = __floats2half2_rn(a, b);
    return *(unsigned*)&h;
}

__device__ __forceinline__ void mma16(float* c,
    unsigned a0, unsigned a1, unsigned a2, unsigned a3,
    unsigned b0, unsigned b1)
{
    asm volatile(
        "mma.sync.aligned.m16n8k16.row.col.f32.f16.f16.f32 "
        "{%0,%1,%2,%3},{%4,%5,%6,%7},{%8,%9},{%0,%1,%2,%3};"
        : "+f"(c[0]), "+f"(c[1]), "+f"(c[2]), "+f"(c[3])
        : "r"(a0), "r"(a1), "r"(a2), "r"(a3), "r"(b0), "r"(b1));
}

__device__ __forceinline__ void ldsm4(unsigned& r0, unsigned& r1,
                                      unsigned& r2, unsigned& r3,
                                      const __half* p)
{
    unsigned a = (unsigned)__cvta_generic_to_shared(p);
    asm volatile("ldmatrix.sync.aligned.m8n8.x4.shared.b16 {%0,%1,%2,%3}, [%4];"
        : "=r"(r0), "=r"(r1), "=r"(r2), "=r"(r3) : "r"(a));
}

// 2^t via FMA-pipe polynomial (no MUFU).
__device__ __forceinline__ float exp2_poly(float t) {
    t = fmaxf(t, -126.0f);
    float z = t + 12582912.0f;
    int   ei = __float_as_int(z) - 0x4B400000;
    float f = t - (float)ei;
    float p = 1.3333558e-3f;
    p = fmaf(p, f, 9.6181291e-3f);
    p = fmaf(p, f, 5.5504109e-2f);
    p = fmaf(p, f, 2.4022651e-1f);
    p = fmaf(p, f, 6.9314718e-1f);
    p = fmaf(p, f, 1.0f);
    return __int_as_float(__float_as_int(p) + (ei << 23));
}

__device__ __forceinline__ void cpa16(__half* dst_smem, const __half* src_gmem) {
    unsigned d = (unsigned)__cvta_generic_to_shared(dst_smem);
    asm volatile("cp.async.cg.shared.global [%0], [%1], 16;" :: "r"(d), "l"(src_gmem));
}
#define CP_COMMIT() asm volatile("cp.async.commit_group;")
#define CP_WAIT0()  asm volatile("cp.async.wait_group 0;" ::: "memory")
#define CP_WAIT1()  asm volatile("cp.async.wait_group 1;" ::: "memory")

// ---------------- f32 -> half elementwise (x) ----------------
__global__ __launch_bounds__(256) void conv_h(const float* __restrict__ in,
                                              __half* __restrict__ out)
{
    int i = blockIdx.x * 256 + threadIdx.x;
    float4 v = *(const float4*)(in + (size_t)i * 4);
    *(uint2*)(out + (size_t)i * 4) = make_uint2(packh2(v.x, v.y), packh2(v.z, v.w));
}

// ---------------- transpose+convert: in[K][N] f32 -> out[N][K] half ----------------
__global__ __launch_bounds__(256) void transp_h(const float* __restrict__ in,
                                                __half* __restrict__ out,
                                                int K, int N)
{
    __shared__ __half tile[32][33];
    const int n0 = blockIdx.x * 32;
    const int k0 = blockIdx.y * 32;
    const int tx = threadIdx.x & 31;
    const int ty = threadIdx.x >> 5;
#pragma unroll
    for (int j = 0; j < 4; j++) {
        int kr = ty + j * 8;
        tile[kr][tx] = __float2half(in[(size_t)(k0 + kr) * N + n0 + tx]);
    }
    __syncthreads();
#pragma unroll
    for (int j = 0; j < 4; j++) {
        int nr = ty + j * 8;
        out[(size_t)(n0 + nr) * K + k0 + tx] = tile[tx][nr];
    }
}

// ================= GEMM mainloop (shared by both gemm kernels) ==================
// BM=128, BN=128, BK=64, 256 threads = 8 warps, warp tile 32x64; ldmatrix frags.
#define GP 72     // smem pitch (halfs): 144B rows, 16B-aligned, conflict-free

#define GEMM_MAINLOOP(A_, Bt_, K_)                                              \
    const int tid  = threadIdx.x;                                               \
    const int w    = tid >> 5;                                                  \
    const int lane = tid & 31;                                                  \
    const int grp  = lane >> 2;                                                 \
    const int t4   = lane & 3;                                                  \
    const int mw   = (w >> 1) * 32;                                             \
    const int nw   = (w & 1) * 64;                                              \
    const int m0   = blockIdx.y * 128;                                          \
    const int n0   = blockIdx.x * 128;                                          \
    const int arow = lane & 15;                                                 \
    const int acol = (lane >> 4) << 3;                                          \
    const int brow = (lane & 7) + ((lane >> 4) << 3);                           \
    const int bcol = ((lane >> 3) & 1) << 3;                                    \
    __half* As = smg;                                                           \
    __half* Bs = smg + 2 * 128 * GP;                                            \
    float acc[2][8][4];                                                         \
    _Pragma("unroll")                                                           \
    for (int mf = 0; mf < 2; mf++)                                              \
        _Pragma("unroll")                                                       \
        for (int nc = 0; nc < 8; nc++)                                          \
            _Pragma("unroll")                                                   \
            for (int j = 0; j < 4; j++) acc[mf][nc][j] = 0.f;                   \
    const int nk = (K_) / 64;                                                   \
    _Pragma("unroll")                                                           \
    for (int it = 0; it < 4; it++) {                                            \
        int c = tid + it * 256;                                                 \
        int r = c >> 3;                                                         \
        int o8 = (c & 7) << 3;                                                  \
        cpa16(As + r * GP + o8, (A_) + (size_t)(m0 + r) * (K_) + o8);           \
        cpa16(Bs + r * GP + o8, (Bt_) + (size_t)(n0 + r) * (K_) + o8);          \
    }                                                                           \
    CP_COMMIT();                                                                \
    for (int i = 0; i < nk; i++) {                                              \
        if (i + 1 < nk) {                                                       \
            const int kn = (i + 1) * 64;                                        \
            __half* An = As + ((i + 1) & 1) * 128 * GP;                         \
            __half* Bn = Bs + ((i + 1) & 1) * 128 * GP;                         \
            _Pragma("unroll")                                                   \
            for (int it = 0; it < 4; it++) {                                    \
                int c = tid + it * 256;                                         \
                int r = c >> 3;                                                 \
                int o8 = (c & 7) << 3;                                          \
                cpa16(An + r * GP + o8, (A_) + (size_t)(m0 + r) * (K_) + kn + o8); \
                cpa16(Bn + r * GP + o8, (Bt_) + (size_t)(n0 + r) * (K_) + kn + o8); \
            }                                                                   \
            CP_COMMIT();                                                        \
            CP_WAIT1();                                                         \
        } else {                                                                \
            CP_WAIT0();                                                         \
        }                                                                       \
        __syncthreads();                                                        \
        const __half* Ac = As + (i & 1) * 128 * GP;                             \
        const __half* Bc = Bs + (i & 1) * 128 * GP;                             \
        _Pragma("unroll")                                                       \
        for (int ks = 0; ks < 4; ks++) {                                        \
            unsigned a[2][4];                                                   \
            ldsm4(a[0][0], a[0][1], a[0][2], a[0][3],                           \
                  Ac + (mw + arow) * GP + ks * 16 + acol);                      \
            ldsm4(a[1][0], a[1][1], a[1][2], a[1][3],                           \
                  Ac + (mw + 16 + arow) * GP + ks * 16 + acol);                 \
            _Pragma("unroll")                                                   \
            for (int nc0 = 0; nc0 < 8; nc0 += 2) {                              \
                unsigned b0, b1, b2, b3;                                        \
                ldsm4(b0, b1, b2, b3,                                           \
                      Bc + (nw + nc0 * 8 + brow) * GP + ks * 16 + bcol);        \
                mma16(acc[0][nc0],     a[0][0], a[0][1], a[0][2], a[0][3], b0, b1); \
                mma16(acc[1][nc0],     a[1][0], a[1][1], a[1][2], a[1][3], b0, b1); \
                mma16(acc[0][nc0 + 1], a[0][0], a[0][1], a[0][2], a[0][3], b2, b3); \
                mma16(acc[1][nc0 + 1], a[1][0], a[1][1], a[1][2], a[1][3], b2, b3); \
            }                                                                   \
        }                                                                       \
        __syncthreads();                                                        \
    }

// ---------------- QKV GEMM with fused bias + RoPE + scatter epilogue ------------
__global__ __launch_bounds__(256) void gemm_qkv(
    const __half* __restrict__ A, const __half* __restrict__ Bt,
    const float* __restrict__ bias,
    const float* __restrict__ cosb, const float* __restrict__ sinb)
{
    extern __shared__ __half smg[];
    GEMM_MAINLOOP(A, Bt, EMBD)

    // epilogue: bias, then RoPE (q,k regions) or pass-through (v region)
    const int region = n0 >> 10;                 // 0=q, 1=k, 2=v
    const int ccbase = (n0 & 1023) + nw;
    __half* dst = (region == 0) ? g_qh : (region == 1) ? g_kh : g_vh;

#pragma unroll
    for (int mf = 0; mf < 2; mf++) {
#pragma unroll
        for (int hh = 0; hh < 2; hh++) {
            int m = m0 + mw + mf * 16 + hh * 8 + grp;
            int t = m & (SEQ - 1);
            int b = m >> 11;
#pragma unroll
            for (int nc = 0; nc < 8; nc++) {
                int cc = ccbase + nc * 8 + 2 * t4;
                float v0 = acc[mf][nc][2 * hh]     + bias[region * 1024 + cc];
                float v1 = acc[mf][nc][2 * hh + 1] + bias[region * 1024 + cc + 1];
                int hd = cc >> 6;
                int d  = cc & 63;
                size_t o = ((size_t)((b * NHEAD + hd) * SEQ + t)) * HDIM + d;
                if (region < 2) {
                    float c = cosb[t * 32 + (d >> 1)];
                    float s = sinb[t * 32 + (d >> 1)];
                    *(unsigned*)(dst + o) = packh2(v0 * c - v1 * s, v0 * s + v1 * c);
                } else {
                    *(unsigned*)(dst + o) = packh2(v0, v1);
                }
            }
        }
    }
}

// ---------------- proj GEMM: bias + f32 output ----------------
__global__ __launch_bounds__(256) void gemm_proj(
    const __half* __restrict__ A, const __half* __restrict__ Bt,
    const float* __restrict__ bias, float* __restrict__ C)
{
    extern __shared__ __half smg[];
    GEMM_MAINLOOP(A, Bt, EMBD)

#pragma unroll
    for (int mf = 0; mf < 2; mf++) {
#pragma unroll
        for (int hh = 0; hh < 2; hh++) {
            int m = m0 + mw + mf * 16 + hh * 8 + grp;
            float* crow = C + (size_t)m * EMBD + n0 + nw;
#pragma unroll
            for (int nc = 0; nc < 8; nc++) {
                int c = nc * 8 + 2 * t4;
                float2 o;
                o.x = acc[mf][nc][2 * hh]     + bias[n0 + nw + c];
                o.y = acc[mf][nc][2 * hh + 1] + bias[n0 + nw + c + 1];
                *(float2*)(crow + c) = o;
            }
        }
    }
}

// ---------------- V transpose: g_vh [bh][t][d] -> g_vt [bh][d][t] ----------------
#define VSP 68
__global__ __launch_bounds__(256) void v_transp()
{
    __shared__ __half sv[64 * VSP];
    const int tt = blockIdx.x;
    const int bh = blockIdx.y;
    const int tid = threadIdx.x;

#pragma unroll
    for (int it = 0; it < 8; it++) {
        int slot = tid + it * 256;        // 0..2047 = (tr, i)
        int i  = slot & 31;
        int tr = slot >> 5;
        unsigned u = *(const unsigned*)(g_vh + ((size_t)(bh * SEQ + tt * 64 + tr)) * HDIM + 2 * i);
        __half2 hv = *(__half2*)&u;
        sv[(2 * i) * VSP + tr]     = __low2half(hv);
        sv[(2 * i + 1) * VSP + tr] = __high2half(hv);
    }
    __syncthreads();

#pragma unroll
    for (int it = 0; it < 4; it++) {
        int slot = tid + it * 256;
        int d  = slot >> 4;
        int c4 = (slot & 15) << 2;
        uint2 u = *(const uint2*)(sv + d * VSP + c4);
        *(uint2*)(g_vt + ((size_t)(bh * HDIM + d)) * SEQ + tt * 64 + c4) = u;
    }
}

// ---------------- flash attention: 8 warps x 16 rows, fp16 mma + ldmatrix --------
#define AP 72
__global__ __launch_bounds__(256) void attn_h()
{
    extern __shared__ __half sm[];
    __half* Qs  = sm;                        // 128*72
    __half* Kb0 = sm + 128 * AP;             // 2 x 64*72
    __half* Vb0 = sm + 128 * AP + 2 * 64 * AP;

    const int qt = (int)gridDim.x - 1 - (int)blockIdx.x;
    const int bh = blockIdx.y;
    const int b  = bh >> 4;
    const int h  = bh & 15;
    const __half* qp = g_qh + (size_t)bh * SEQ * HDIM;
    const __half* kp = g_kh + (size_t)bh * SEQ * HDIM;
    const __half* vp = g_vt + (size_t)bh * HDIM * SEQ;
    const int q0 = qt * 128;

    const int tid  = threadIdx.x;
    const int w    = tid >> 5;
    const int lane = tid & 31;
    const int grp  = lane >> 2;
    const int t4   = lane & 3;
    const int mw   = w * 16;

    const int arow = lane & 15;
    const int acol = (lane >> 4) << 3;
    const int brow = (lane & 7) + ((lane >> 4) << 3);
    const int bcol = ((lane >> 3) & 1) << 3;

    // prologue: stage Q + tile 0 K/V
#pragma unroll
    for (int it = 0; it < 4; it++) {
        int slot = tid + it * 256;
        int r  = slot >> 3;
        int c8 = (slot & 7) << 3;
        cpa16(Qs + r * AP + c8, qp + (size_t)(q0 + r) * HDIM + c8);
    }
#pragma unroll
    for (int it = 0; it < 2; it++) {
        int slot = tid + it * 256;
        int r  = slot >> 3;
        int c8 = (slot & 7) << 3;
        cpa16(Kb0 + r * AP + c8, kp + (size_t)r * HDIM + c8);
        cpa16(Vb0 + r * AP + c8, vp + (size_t)r * SEQ + c8);
    }
    CP_COMMIT();

    float O[8][4];
#pragma unroll
    for (int nc = 0; nc < 8; nc++)
#pragma unroll
        for (int j = 0; j < 4; j++) O[nc][j] = 0.f;
    float mrow[2] = {-INFINITY, -INFINITY};
    float lrow[2] = {0.f, 0.f};

    const int kt_max = 2 * qt + 1;
    for (int kt = 0; kt <= kt_max; kt++) {
        const int k0 = kt * 64;
        if (kt < kt_max) {
            const int kn = k0 + 64;
            __half* Kn = Kb0 + ((kt + 1) & 1) * 64 * AP;
            __half* Vn = Vb0 + ((kt + 1) & 1) * 64 * AP;
#pragma unroll
            for (int it = 0; it < 2; it++) {
                int slot = tid + it * 256;
                int r  = slot >> 3;
                int c8 = (slot & 7) << 3;
                cpa16(Kn + r * AP + c8, kp + (size_t)(kn + r) * HDIM + c8);
                cpa16(Vn + r * AP + c8, vp + (size_t)r * SEQ + kn + c8);
            }
            CP_COMMIT();
            CP_WAIT1();
        } else {
            CP_WAIT0();
        }
        __syncthreads();

        if (k0 <= q0 + mw + 15) {
            const __half* Kb = Kb0 + (kt & 1) * 64 * AP;
            const __half* Vb = Vb0 + (kt & 1) * 64 * AP;

            // ---- S = Q K^T ----
            float S[8][4];
#pragma unroll
            for (int nc = 0; nc < 8; nc++)
#pragma unroll
                for (int j = 0; j < 4; j++) S[nc][j] = 0.f;

#pragma unroll
            for (int ks = 0; ks < 4; ks++) {
                unsigned a0, a1, a2, a3;
                ldsm4(a0, a1, a2, a3, Qs + (mw + arow) * AP + ks * 16 + acol);
#pragma unroll
                for (int nc0 = 0; nc0 < 8; nc0 += 2) {
                    unsigned b0, b1, b2, b3;
                    ldsm4(b0, b1, b2, b3, Kb + (nc0 * 8 + brow) * AP + ks * 16 + bcol);
                    mma16(S[nc0],     a0, a1, a2, a3, b0, b1);
                    mma16(S[nc0 + 1], a0, a1, a2, a3, b2, b3);
                }
            }

            // ---- causal mask ----
            if (k0 + 63 > q0 + mw) {
                int r0g = q0 + mw + grp;
                int r1g = r0g + 8;
#pragma unroll
                for (int nc = 0; nc < 8; nc++) {
                    int col = k0 + nc * 8 + 2 * t4;
                    if (col     > r0g) S[nc][0] = -INFINITY;
                    if (col + 1 > r0g) S[nc][1] = -INFINITY;
                    if (col     > r1g) S[nc][2] = -INFINITY;
                    if (col + 1 > r1g) S[nc][3] = -INFINITY;
                }
            }

            // ---- online softmax (FMA-pipe exp2) ----
#pragma unroll
            for (int hh = 0; hh < 2; hh++) {
                float mx = -INFINITY;
#pragma unroll
                for (int nc = 0; nc < 8; nc++)
                    mx = fmaxf(mx, fmaxf(S[nc][2 * hh], S[nc][2 * hh + 1]));
                mx = fmaxf(mx, __shfl_xor_sync(0xffffffffu, mx, 1));
                mx = fmaxf(mx, __shfl_xor_sync(0xffffffffu, mx, 2));
                mx *= 0.125f;

                float mold = mrow[hh];
                float mnew = fmaxf(mold, mx);
                float al   = exp2_poly((mold - mnew) * LOG2E);
                mrow[hh] = mnew;
                float mb = mnew * LOG2E;

                float sum = 0.f;
#pragma unroll
                for (int nc = 0; nc < 8; nc++) {
                    float p0 = exp2_poly(fmaf(S[nc][2 * hh],     0.1803368801f, -mb));
                    float p1 = exp2_poly(fmaf(S[nc][2 * hh + 1], 0.1803368801f, -mb));
                    S[nc][2 * hh]     = p0;
                    S[nc][2 * hh + 1] = p1;
                    sum += p0 + p1;
                }
                sum += __shfl_xor_sync(0xffffffffu, sum, 1);
                sum += __shfl_xor_sync(0xffffffffu, sum, 2);
                lrow[hh] = lrow[hh] * al + sum;

#pragma unroll
                for (int nc = 0; nc < 8; nc++) {
                    O[nc][2 * hh]     *= al;
                    O[nc][2 * hh + 1] *= al;
                }
            }

            // ---- O += P V (P register-resident as A-fragments) ----
#pragma unroll
            for (int ks = 0; ks < 4; ks++) {
                unsigned a0 = packh2(S[2 * ks][0],     S[2 * ks][1]);
                unsigned a1 = packh2(S[2 * ks][2],     S[2 * ks][3]);
                unsigned a2 = packh2(S[2 * ks + 1][0], S[2 * ks + 1][1]);
                unsigned a3 = packh2(S[2 * ks + 1][2], S[2 * ks + 1][3]);
#pragma unroll
                for (int nc0 = 0; nc0 < 8; nc0 += 2) {
                    unsigned b0, b1, b2, b3;
                    ldsm4(b0, b1, b2, b3, Vb + (nc0 * 8 + brow) * AP + ks * 16 + bcol);
                    mma16(O[nc0],     a0, a1, a2, a3, b0, b1);
                    mma16(O[nc0 + 1], a0, a1, a2, a3, b2, b3);
                }
            }
        }
        __syncthreads();
    }

    // ---- epilogue: normalize, write half to g_atth [B,T,C] ----
#pragma unroll
    for (int hh = 0; hh < 2; hh++) {
        float inv = 1.f / lrow[hh];
        int row = q0 + mw + hh * 8 + grp;
        size_t base = ((size_t)(b * SEQ + row)) * EMBD + h * HDIM;
#pragma unroll
        for (int nc = 0; nc < 8; nc++) {
            int c = nc * 8 + 2 * t4;
            *(unsigned*)(g_atth + base + c) =
                packh2(O[nc][2 * hh] * inv, O[nc][2 * hh + 1] * inv);
        }
    }
}

// ---------------- launcher ----------------
extern "C" void kernel_launch(void* const* d_in, const int* in_sizes, int n_in,
                              void* d_out, int out_size)
{
    const float* x     = (const float*)d_in[0];
    const float* Wqkv  = (const float*)d_in[1];
    const float* bqkv  = (const float*)d_in[2];
    const float* Wproj = (const float*)d_in[3];
    const float* bproj = (const float*)d_in[4];
    const float* cosb  = (const float*)d_in[5];
    const float* sinb  = (const float*)d_in[6];
    float* out = (float*)d_out;

    void *p_xh, *p_wqkvt, *p_wprojt, *p_atth;
    cudaGetSymbolAddress(&p_xh, g_xh);
    cudaGetSymbolAddress(&p_wqkvt, g_wqkvt);
    cudaGetSymbolAddress(&p_wprojt, g_wprojt);
    cudaGetSymbolAddress(&p_atth, g_atth);

    // 0) pre-convert / pre-transpose
    conv_h<<<(BT * EMBD) / (256 * 4), 256>>>(x, (__half*)p_xh);
    transp_h<<<dim3(QKVN / 32, EMBD / 32), 256>>>(Wqkv, (__half*)p_wqkvt, EMBD, QKVN);
    transp_h<<<dim3(EMBD / 32, EMBD / 32), 256>>>(Wproj, (__half*)p_wprojt, EMBD, EMBD);

    const int gsm = 4 * 128 * GP * sizeof(__half);   // 73728 B
    cudaFuncSetAttribute(gemm_qkv, cudaFuncAttributeMaxDynamicSharedMemorySize, gsm);
    cudaFuncSetAttribute(gemm_proj, cudaFuncAttributeMaxDynamicSharedMemorySize, gsm);

    // 1) QKV GEMM with fused bias + RoPE epilogue
    gemm_qkv<<<dim3(QKVN / 128, BT / 128), 256, gsm>>>(
        (const __half*)p_xh, (const __half*)p_wqkvt, bqkv, cosb, sinb);

    // 2) V transpose [bh][t][d] -> [bh][d][t]
    v_transp<<<dim3(SEQ / 64, BATCH * NHEAD), 256>>>();

    // 3) causal flash attention
    const int asm_bytes = (128 * AP + 4 * 64 * AP) * sizeof(__half);   // 55296
    cudaFuncSetAttribute(attn_h, cudaFuncAttributeMaxDynamicSharedMemorySize, asm_bytes);
    attn_h<<<dim3(SEQ / 128, BATCH * NHEAD), 256, asm_bytes>>>();

    // 4) output projection
    gemm_proj<<<dim3(EMBD / 128, BT / 128), 256, gsm>>>(
        (const __half*)p_atth, (const __half*)p_wprojt, bproj, out);
}